// round 1
// baseline (speedup 1.0000x reference)
#include <cuda_runtime.h>
#include <cstdint>

#define NB  8
#define NC  256
#define NCQ 32
#define NN  4096
#define TN  64
#define TM  32

// ---------------- scratch (no allocs allowed) ----------------
__device__ float g_q[NB * NCQ * NN];
__device__ float g_k[NB * NCQ * NN];
__device__ float g_v[NB * NC  * NN];

// ---------------- packed f32x2 helpers (sm_103a) ----------------
__device__ __forceinline__ unsigned long long pack2(float a, float b) {
    unsigned long long r;
    asm("mov.b64 %0, {%1, %2};" : "=l"(r) : "f"(a), "f"(b));
    return r;
}
__device__ __forceinline__ void fma2(unsigned long long& d, unsigned long long a, unsigned long long b) {
    asm("fma.rn.f32x2 %0, %1, %2, %0;" : "+l"(d) : "l"(a), "l"(b));
}
__device__ __forceinline__ void mul2(unsigned long long& d, unsigned long long a) {
    asm("mul.rn.f32x2 %0, %0, %1;" : "+l"(d) : "l"(a));
}
__device__ __forceinline__ float2 unpack2(unsigned long long v) {
    float lo, hi;
    asm("mov.b64 {%0, %1}, %2;" : "=f"(lo), "=f"(hi) : "l"(v));
    return make_float2(lo, hi);
}

// ---------------- projection kernel ----------------
// q/k/v = W @ x + b  (per batch, per pixel). grid (NN/256, 10, NB), block 256.
// Block computes a [32 out x 256 n] tile, looping c in chunks of 32.
__global__ void __launch_bounds__(256) proj_kernel(
    const float* __restrict__ x,
    const float* __restrict__ wq, const float* __restrict__ bq,
    const float* __restrict__ wk, const float* __restrict__ bk,
    const float* __restrict__ wv, const float* __restrict__ bv)
{
    __shared__ float xs[32][256];
    __shared__ float ws[32][33];

    const int b  = blockIdx.z;
    const int n0 = blockIdx.x * 256;
    const int o0 = blockIdx.y * 32;
    const int tid = threadIdx.x;
    const int tx = tid & 63;   // n-group: n = tx*4 + k
    const int ty = tid >> 6;   // o-group: o = ty*8 + i

    float acc[8][4];
#pragma unroll
    for (int i = 0; i < 8; i++)
#pragma unroll
        for (int k = 0; k < 4; k++) acc[i][k] = 0.f;

    for (int cc = 0; cc < NC; cc += 32) {
        __syncthreads();
        // load x tile [32 c][256 n] (float4, coalesced)
#pragma unroll
        for (int p = 0; p < 8; p++) {
            int idx = tid + p * 256;
            int c  = idx >> 6;
            int n4 = idx & 63;
            *(float4*)&xs[c][n4 * 4] =
                *(const float4*)&x[(size_t)(b * NC + cc + c) * NN + n0 + n4 * 4];
        }
        // load w tile [32 o][32 c]
#pragma unroll
        for (int p = 0; p < 4; p++) {
            int idx = tid + p * 256;
            int o  = idx >> 5;
            int c2 = idx & 31;
            int og = o0 + o;
            const float* wsrc;
            if (og < 32)        wsrc = wq + og * NC;
            else if (og < 64)   wsrc = wk + (og - 32) * NC;
            else                wsrc = wv + (og - 64) * NC;
            ws[o][c2] = wsrc[cc + c2];
        }
        __syncthreads();
#pragma unroll
        for (int c = 0; c < 32; c++) {
            float4 xv = *(const float4*)&xs[c][tx * 4];
#pragma unroll
            for (int i = 0; i < 8; i++) {
                float wv_ = ws[ty * 8 + i][c];
                acc[i][0] = fmaf(wv_, xv.x, acc[i][0]);
                acc[i][1] = fmaf(wv_, xv.y, acc[i][1]);
                acc[i][2] = fmaf(wv_, xv.z, acc[i][2]);
                acc[i][3] = fmaf(wv_, xv.w, acc[i][3]);
            }
        }
    }

#pragma unroll
    for (int i = 0; i < 8; i++) {
        int og = o0 + ty * 8 + i;
        float* dst; float bias;
        if (og < 32)      { dst = g_q + (size_t)(b * NCQ + og)        * NN; bias = bq[og]; }
        else if (og < 64) { dst = g_k + (size_t)(b * NCQ + (og - 32)) * NN; bias = bk[og - 32]; }
        else              { dst = g_v + (size_t)(b * NC  + (og - 64)) * NN; bias = bv[og - 64]; }
        float4 v4 = make_float4(acc[i][0] + bias, acc[i][1] + bias,
                                acc[i][2] + bias, acc[i][3] + bias);
        *(float4*)&dst[n0 + tx * 4] = v4;
    }
}

// ---------------- fused attention kernel ----------------
// grid (NN/TN, NB), block 256 (8 warps). Warp w owns rows w*8..w*8+7 of the
// 64-query block; lane owns 8 contiguous output channels. Online softmax.
//
// dynamic smem layout (floats):
//   [0,      8448)  vs[j*260 + c]  (V tile 32x256, pad 260)  UNION  stg[c*33 + r] (epilogue)
//   [8448,  10560)  qs[r*33 + d]   (Q tile 64x32, pad 33)
//   [10560, 11584)  ks[d*32 + j]   (K tile 32x32)
//   [11584, 15680)  ps (as u64[8w][8r][32j]) duplicated (p,p) pairs
#define SM_QS   8448
#define SM_KS  (8448 + 2112)
#define SM_PS  (8448 + 2112 + 1024)
#define SMEM_FLOATS (8448 + 2112 + 1024 + 4096)
#define SMEM_BYTES  (SMEM_FLOATS * 4)

__global__ void __launch_bounds__(256) attn_kernel(float* __restrict__ out,
                                                   const float* __restrict__ gamma)
{
    extern __shared__ float sm[];
    float* vs = sm;
    float* stg = sm;
    float* qs = sm + SM_QS;
    float* ks = sm + SM_KS;
    unsigned long long* ps = (unsigned long long*)(sm + SM_PS);

    const int b    = blockIdx.y;
    const int n0   = blockIdx.x * TN;
    const int tid  = threadIdx.x;
    const int w    = tid >> 5;
    const int lane = tid & 31;
    const int rb   = w * 8;

    // load Q tile [64 r][32 d]
#pragma unroll
    for (int p = 0; p < 8; p++) {
        int idx = tid + p * 256;
        int r = idx & 63;
        int d = idx >> 6;
        qs[r * 33 + d] = g_q[(size_t)(b * NCQ + d) * NN + n0 + r];
    }

    unsigned long long acc[8][4];
#pragma unroll
    for (int r = 0; r < 8; r++)
#pragma unroll
        for (int i = 0; i < 4; i++) acc[r][i] = 0ull;

    float run_m[8], run_l[8];
#pragma unroll
    for (int r = 0; r < 8; r++) { run_m[r] = -1e30f; run_l[r] = 0.f; }

    for (int t = 0; t < NN / TM; t++) {
        const int m0 = t * TM;
        __syncthreads();
        // K tile: ks[d][j]
#pragma unroll
        for (int p = 0; p < 4; p++) {
            int idx = tid + p * 256;
            int j = idx & 31;
            int d = idx >> 5;
            ks[d * 32 + j] = g_k[(size_t)(b * NCQ + d) * NN + m0 + j];
        }
        // V tile: vs[j][c]; warp w loads channels w*32..w*32+31, lane = j
        {
            const float* vsrc = g_v + (size_t)(b * NC + w * 32) * NN + m0 + lane;
#pragma unroll
            for (int ii = 0; ii < 32; ii++)
                vs[lane * 260 + (w * 32 + ii)] = vsrc[(size_t)ii * NN];
        }
        __syncthreads();

        // --- phase 1: logits + online softmax (lane <-> key j) ---
        float e[8];
#pragma unroll
        for (int r = 0; r < 8; r++) e[r] = 0.f;
#pragma unroll
        for (int d = 0; d < 32; d++) {
            float kd = ks[d * 32 + lane];
#pragma unroll
            for (int r = 0; r < 8; r++)
                e[r] = fmaf(qs[(rb + r) * 33 + d], kd, e[r]);
        }
        float corr[8];
#pragma unroll
        for (int r = 0; r < 8; r++) {
            float tm = e[r];
#pragma unroll
            for (int s = 16; s > 0; s >>= 1)
                tm = fmaxf(tm, __shfl_xor_sync(0xffffffffu, tm, s));
            float nm = fmaxf(run_m[r], tm);
            float p  = __expf(e[r] - nm);
            float psum = p;
#pragma unroll
            for (int s = 16; s > 0; s >>= 1)
                psum += __shfl_xor_sync(0xffffffffu, psum, s);
            float cr = __expf(run_m[r] - nm);
            run_l[r] = run_l[r] * cr + psum;
            run_m[r] = nm;
            corr[r] = cr;
            ps[(w * 8 + r) * 32 + lane] = pack2(p, p);
        }
        __syncwarp();

        // rescale accumulators by exp(m_old - m_new)
#pragma unroll
        for (int r = 0; r < 8; r++) {
            unsigned long long cc2 = pack2(corr[r], corr[r]);
#pragma unroll
            for (int i = 0; i < 4; i++) mul2(acc[r][i], cc2);
        }

        // --- phase 2: acc += P * V (lane <-> channels lane*8..lane*8+7) ---
#pragma unroll 8
        for (int j = 0; j < TM; j++) {
            const ulonglong2 va = *(const ulonglong2*)(vs + j * 260 + lane * 8);
            const ulonglong2 vb = *(const ulonglong2*)(vs + j * 260 + lane * 8 + 4);
#pragma unroll
            for (int r = 0; r < 8; r++) {
                unsigned long long pp = ps[(w * 8 + r) * 32 + j];
                fma2(acc[r][0], pp, va.x);
                fma2(acc[r][1], pp, va.y);
                fma2(acc[r][2], pp, vb.x);
                fma2(acc[r][3], pp, vb.y);
            }
        }
    }

    // ---------------- epilogue: normalize, gamma-residual, floor-quantize,
    // transpose through smem for coalesced [c][n] writes (two 32-row halves).
    const float gm = __ldg(gamma);
#pragma unroll
    for (int half = 0; half < 2; half++) {
        __syncthreads();
        if ((w >> 2) == half) {
#pragma unroll
            for (int r = 0; r < 8; r++) {
                int lr = rb + r - half * 32;
                float inv_l = 1.0f / run_l[r];
#pragma unroll
                for (int i = 0; i < 4; i++) {
                    float2 f = unpack2(acc[r][i]);
                    int c0 = lane * 8 + i * 2;
                    float o0v = f.x * inv_l;
                    float o1v = f.y * inv_l;
                    float r0 = gm * o0v + o0v;
                    float r1 = gm * o1v + o1v;
                    stg[(c0    ) * 33 + lr] = floorf(r0 * 256.f) * (1.f / 256.f);
                    stg[(c0 + 1) * 33 + lr] = floorf(r1 * 256.f) * (1.f / 256.f);
                }
            }
        }
        __syncthreads();
        {
            int rr = tid & 31;
            int cb = tid >> 5;
#pragma unroll
            for (int ii = 0; ii < 32; ii++) {
                int c = cb * 32 + ii;
                out[(size_t)(b * NC + c) * NN + n0 + half * 32 + rr] = stg[c * 33 + rr];
            }
        }
    }
}

// ---------------- launch ----------------
extern "C" void kernel_launch(void* const* d_in, const int* in_sizes, int n_in,
                              void* d_out, int out_size)
{
    const float* x     = (const float*)d_in[0];
    const float* wq    = (const float*)d_in[1];
    const float* bq    = (const float*)d_in[2];
    const float* wk    = (const float*)d_in[3];
    const float* bk    = (const float*)d_in[4];
    const float* wv    = (const float*)d_in[5];
    const float* bv    = (const float*)d_in[6];
    const float* gamma = (const float*)d_in[7];
    float* out = (float*)d_out;

    dim3 gp(NN / 256, 10, NB);
    proj_kernel<<<gp, 256>>>(x, wq, bq, wk, bk, wv, bv);

    cudaFuncSetAttribute(attn_kernel, cudaFuncAttributeMaxDynamicSharedMemorySize, SMEM_BYTES);
    dim3 ga(NN / TN, NB);
    attn_kernel<<<ga, 256, SMEM_BYTES>>>(out, gamma);
}

// round 2
// speedup vs baseline: 1.3991x; 1.3991x over previous
#include <cuda_runtime.h>
#include <cstdint>

#define NB  8
#define NC  256
#define NCQ 32
#define NN  4096
#define TN  64
#define TM  32

// ---------------- scratch (no allocs allowed) ----------------
__device__ float g_q[NB * NCQ * NN];
__device__ float g_k[NB * NCQ * NN];
__device__ float g_v[NB * NC  * NN];

// ---------------- packed f32x2 helpers (sm_103a) ----------------
__device__ __forceinline__ unsigned long long pack2(float a, float b) {
    unsigned long long r;
    asm("mov.b64 %0, {%1, %2};" : "=l"(r) : "f"(a), "f"(b));
    return r;
}
__device__ __forceinline__ void fma2(unsigned long long& d, unsigned long long a, unsigned long long b) {
    asm("fma.rn.f32x2 %0, %1, %2, %0;" : "+l"(d) : "l"(a), "l"(b));
}
__device__ __forceinline__ float2 unpack2(unsigned long long v) {
    float lo, hi;
    asm("mov.b64 {%0, %1}, %2;" : "=f"(lo), "=f"(hi) : "l"(v));
    return make_float2(lo, hi);
}

// ---------------- projection kernel ----------------
__global__ void __launch_bounds__(256) proj_kernel(
    const float* __restrict__ x,
    const float* __restrict__ wq, const float* __restrict__ bq,
    const float* __restrict__ wk, const float* __restrict__ bk,
    const float* __restrict__ wv, const float* __restrict__ bv)
{
    __shared__ float xs[32][256];
    __shared__ float ws[32][33];

    const int b  = blockIdx.z;
    const int n0 = blockIdx.x * 256;
    const int o0 = blockIdx.y * 32;
    const int tid = threadIdx.x;
    const int tx = tid & 63;
    const int ty = tid >> 6;

    float acc[8][4];
#pragma unroll
    for (int i = 0; i < 8; i++)
#pragma unroll
        for (int k = 0; k < 4; k++) acc[i][k] = 0.f;

    for (int cc = 0; cc < NC; cc += 32) {
        __syncthreads();
#pragma unroll
        for (int p = 0; p < 8; p++) {
            int idx = tid + p * 256;
            int c  = idx >> 6;
            int n4 = idx & 63;
            *(float4*)&xs[c][n4 * 4] =
                *(const float4*)&x[(size_t)(b * NC + cc + c) * NN + n0 + n4 * 4];
        }
#pragma unroll
        for (int p = 0; p < 4; p++) {
            int idx = tid + p * 256;
            int o  = idx >> 5;
            int c2 = idx & 31;
            int og = o0 + o;
            const float* wsrc;
            if (og < 32)        wsrc = wq + og * NC;
            else if (og < 64)   wsrc = wk + (og - 32) * NC;
            else                wsrc = wv + (og - 64) * NC;
            ws[o][c2] = wsrc[cc + c2];
        }
        __syncthreads();
#pragma unroll
        for (int c = 0; c < 32; c++) {
            float4 xv = *(const float4*)&xs[c][tx * 4];
#pragma unroll
            for (int i = 0; i < 8; i++) {
                float wv_ = ws[ty * 8 + i][c];
                acc[i][0] = fmaf(wv_, xv.x, acc[i][0]);
                acc[i][1] = fmaf(wv_, xv.y, acc[i][1]);
                acc[i][2] = fmaf(wv_, xv.z, acc[i][2]);
                acc[i][3] = fmaf(wv_, xv.w, acc[i][3]);
            }
        }
    }

#pragma unroll
    for (int i = 0; i < 8; i++) {
        int og = o0 + ty * 8 + i;
        float* dst; float bias;
        if (og < 32)      { dst = g_q + (size_t)(b * NCQ + og)        * NN; bias = bq[og]; }
        else if (og < 64) { dst = g_k + (size_t)(b * NCQ + (og - 32)) * NN; bias = bk[og - 32]; }
        else              { dst = g_v + (size_t)(b * NC  + (og - 64)) * NN; bias = bv[og - 64]; }
        float4 v4 = make_float4(acc[i][0] + bias, acc[i][1] + bias,
                                acc[i][2] + bias, acc[i][3] + bias);
        *(float4*)&dst[n0 + tx * 4] = v4;
    }
}

// ---------------- fused attention kernel ----------------
// grid (NN/TN, NB), block 256 (8 warps). Warp w owns rows w*8..w*8+7.
// Lane owns channels {4*lane..4*lane+3} U {128+4*lane..128+4*lane+3}
// (conflict-free LDS.128 on V).
// Fixed-max softmax: p = exp(e) directly (logits bounded << 88), per-lane
// partial row-sums, single warp reduction at the end.
//
// smem floats:
//   [0,      8448)  vs[j*260 + c]  (V tile 32x256, pad 260)  UNION stg (epilogue)
//   [8448,  10496)  qs2[d*64 + r]  (Q tile, d-major, rows contiguous)
//   [10496, 11520)  ks[d*32 + j]
//   [11520, 13568)  ps[w][j][r]    (8 warps x 32 keys x 8 rows, scalar p)
#define SM_QS   8448
#define SM_KS  (8448 + 2048)
#define SM_PS  (8448 + 2048 + 1024)
#define SMEM_FLOATS (8448 + 2048 + 1024 + 2048)
#define SMEM_BYTES  (SMEM_FLOATS * 4)

__global__ void __launch_bounds__(256, 2) attn_kernel(float* __restrict__ out,
                                                      const float* __restrict__ gamma)
{
    extern __shared__ float sm[];
    float* vs  = sm;
    float* stg = sm;
    float* qs2 = sm + SM_QS;
    float* ks  = sm + SM_KS;

    const int b    = blockIdx.y;
    const int n0   = blockIdx.x * TN;
    const int tid  = threadIdx.x;
    const int w    = tid >> 5;
    const int lane = tid & 31;
    const int rb   = w * 8;
    float* psw = sm + SM_PS + w * 256;

    // Q staging: qs2[d][r], rows contiguous (for pair broadcasts)
#pragma unroll
    for (int p = 0; p < 2; p++) {
        int idx = p * 256 + tid;
        int d = idx >> 4;
        int r4 = (idx & 15) * 4;
        *(float4*)&qs2[d * 64 + r4] =
            *(const float4*)&g_q[((size_t)b * NCQ + d) * NN + n0 + r4];
    }

    unsigned long long acc[8][4];
#pragma unroll
    for (int r = 0; r < 8; r++)
#pragma unroll
        for (int i = 0; i < 4; i++) acc[r][i] = 0ull;

    float run_l[8];
#pragma unroll
    for (int r = 0; r < 8; r++) run_l[r] = 0.f;

    for (int t = 0; t < NN / TM; t++) {
        const int m0 = t * TM;
        __syncthreads();
        // K tile: ks[d][j] (one float4 per thread)
        {
            int d = tid >> 3;
            int j4 = (tid & 7) * 4;
            *(float4*)&ks[d * 32 + j4] =
                *(const float4*)&g_k[((size_t)b * NCQ + d) * NN + m0 + j4];
        }
        // V tile: vs[j][c]; warp w stages channels w*32..w*32+31 via float4 loads
        {
            const float* vbase = g_v + ((size_t)b * NC + w * 32) * NN + m0;
#pragma unroll
            for (int p = 0; p < 8; p++) {
                int q  = p * 32 + lane;
                int ch = q >> 3;
                int j4 = (q & 7) * 4;
                float4 vv = *(const float4*)&vbase[(size_t)ch * NN + j4];
                float* dst = vs + w * 32 + ch;
                dst[(j4 + 0) * 260] = vv.x;
                dst[(j4 + 1) * 260] = vv.y;
                dst[(j4 + 2) * 260] = vv.z;
                dst[(j4 + 3) * 260] = vv.w;
            }
        }
        __syncthreads();

        // --- phase 1: logits (f32x2, rows paired), exp, P store ---
        unsigned long long ep[4] = {0ull, 0ull, 0ull, 0ull};
#pragma unroll
        for (int d = 0; d < 32; d++) {
            float kd = ks[d * 32 + lane];
            unsigned long long kd2 = pack2(kd, kd);
            ulonglong2 qa = *(const ulonglong2*)&qs2[d * 64 + rb];
            ulonglong2 qb = *(const ulonglong2*)&qs2[d * 64 + rb + 4];
            fma2(ep[0], qa.x, kd2);
            fma2(ep[1], qa.y, kd2);
            fma2(ep[2], qb.x, kd2);
            fma2(ep[3], qb.y, kd2);
        }
        float pst[8];
#pragma unroll
        for (int rp = 0; rp < 4; rp++) {
            float2 e2 = unpack2(ep[rp]);
            pst[2 * rp]     = __expf(e2.x);
            pst[2 * rp + 1] = __expf(e2.y);
            run_l[2 * rp]     += pst[2 * rp];
            run_l[2 * rp + 1] += pst[2 * rp + 1];
        }
        *(float4*)&psw[lane * 8]     = make_float4(pst[0], pst[1], pst[2], pst[3]);
        *(float4*)&psw[lane * 8 + 4] = make_float4(pst[4], pst[5], pst[6], pst[7]);
        __syncwarp();

        // --- phase 2: acc += P * V ---
#pragma unroll 4
        for (int j = 0; j < TM; j++) {
            ulonglong2 va = *(const ulonglong2*)(vs + j * 260 + lane * 4);
            ulonglong2 vb = *(const ulonglong2*)(vs + j * 260 + 128 + lane * 4);
            float4 pA = *(const float4*)(psw + j * 8);
            float4 pB = *(const float4*)(psw + j * 8 + 4);
            unsigned long long pp;
            pp = pack2(pA.x, pA.x);
            fma2(acc[0][0], pp, va.x); fma2(acc[0][1], pp, va.y);
            fma2(acc[0][2], pp, vb.x); fma2(acc[0][3], pp, vb.y);
            pp = pack2(pA.y, pA.y);
            fma2(acc[1][0], pp, va.x); fma2(acc[1][1], pp, va.y);
            fma2(acc[1][2], pp, vb.x); fma2(acc[1][3], pp, vb.y);
            pp = pack2(pA.z, pA.z);
            fma2(acc[2][0], pp, va.x); fma2(acc[2][1], pp, va.y);
            fma2(acc[2][2], pp, vb.x); fma2(acc[2][3], pp, vb.y);
            pp = pack2(pA.w, pA.w);
            fma2(acc[3][0], pp, va.x); fma2(acc[3][1], pp, va.y);
            fma2(acc[3][2], pp, vb.x); fma2(acc[3][3], pp, vb.y);
            pp = pack2(pB.x, pB.x);
            fma2(acc[4][0], pp, va.x); fma2(acc[4][1], pp, va.y);
            fma2(acc[4][2], pp, vb.x); fma2(acc[4][3], pp, vb.y);
            pp = pack2(pB.y, pB.y);
            fma2(acc[5][0], pp, va.x); fma2(acc[5][1], pp, va.y);
            fma2(acc[5][2], pp, vb.x); fma2(acc[5][3], pp, vb.y);
            pp = pack2(pB.z, pB.z);
            fma2(acc[6][0], pp, va.x); fma2(acc[6][1], pp, va.y);
            fma2(acc[6][2], pp, vb.x); fma2(acc[6][3], pp, vb.y);
            pp = pack2(pB.w, pB.w);
            fma2(acc[7][0], pp, va.x); fma2(acc[7][1], pp, va.y);
            fma2(acc[7][2], pp, vb.x); fma2(acc[7][3], pp, vb.y);
        }
    }

    // final row-sum reductions (once, not per tile)
#pragma unroll
    for (int r = 0; r < 8; r++) {
        float s = run_l[r];
#pragma unroll
        for (int sh = 16; sh > 0; sh >>= 1)
            s += __shfl_xor_sync(0xffffffffu, s, sh);
        run_l[r] = 1.0f / s;
    }

    // ---------------- epilogue ----------------
    const float gm = __ldg(gamma);
#pragma unroll
    for (int half = 0; half < 2; half++) {
        __syncthreads();
        if ((w >> 2) == half) {
#pragma unroll
            for (int r = 0; r < 8; r++) {
                int lr = rb + r - half * 32;
                float inv_l = run_l[r];
#pragma unroll
                for (int i = 0; i < 4; i++) {
                    float2 f = unpack2(acc[r][i]);
                    int c0 = (i & 1) * 2 + (i >> 1) * 128 + lane * 4;
                    float o0v = f.x * inv_l;
                    float o1v = f.y * inv_l;
                    float r0 = gm * o0v + o0v;
                    float r1 = gm * o1v + o1v;
                    stg[(c0    ) * 33 + lr] = floorf(r0 * 256.f) * (1.f / 256.f);
                    stg[(c0 + 1) * 33 + lr] = floorf(r1 * 256.f) * (1.f / 256.f);
                }
            }
        }
        __syncthreads();
        {
            int rr = tid & 31;
            int cb = tid >> 5;
#pragma unroll
            for (int ii = 0; ii < 32; ii++) {
                int c = cb * 32 + ii;
                out[(size_t)(b * NC + c) * NN + n0 + half * 32 + rr] = stg[c * 33 + rr];
            }
        }
    }
}

// ---------------- launch ----------------
extern "C" void kernel_launch(void* const* d_in, const int* in_sizes, int n_in,
                              void* d_out, int out_size)
{
    const float* x     = (const float*)d_in[0];
    const float* wq    = (const float*)d_in[1];
    const float* bq    = (const float*)d_in[2];
    const float* wk    = (const float*)d_in[3];
    const float* bk    = (const float*)d_in[4];
    const float* wv    = (const float*)d_in[5];
    const float* bv    = (const float*)d_in[6];
    const float* gamma = (const float*)d_in[7];
    float* out = (float*)d_out;

    dim3 gp(NN / 256, 10, NB);
    proj_kernel<<<gp, 256>>>(x, wq, bq, wk, bk, wv, bv);

    cudaFuncSetAttribute(attn_kernel, cudaFuncAttributeMaxDynamicSharedMemorySize, SMEM_BYTES);
    dim3 ga(NN / TN, NB);
    attn_kernel<<<ga, 256, SMEM_BYTES>>>(out, gamma);
}

// round 4
// speedup vs baseline: 2.0177x; 1.4421x over previous
#include <cuda_runtime.h>
#include <cuda_bf16.h>
#include <cstdint>

#define NB  8
#define NC  256
#define NCQ 32
#define NN  4096
#define MR  64      // query rows per CTA
#define TK  32      // keys per gmem tile

// ---------------- scratch (no allocs allowed) ----------------
__device__ float g_q[NB * NCQ * NN];            // [b][d][n]
__device__ float g_k[NB * NCQ * NN];            // [b][d][n]
__device__ float qt_h[NB * NN * NCQ];           // [b][n][d] tf32-rounded
__device__ float qt_l[NB * NN * NCQ];           // residual (tf32-rounded)
__device__ float kt_h[NB * NN * NCQ];
__device__ float kt_l[NB * NN * NCQ];
__device__ __nv_bfloat16 vv_h[NB * NC * NN];    // [b][ch][n] bf16-hi
__device__ __nv_bfloat16 vv_l[NB * NC * NN];    // bf16 residual

// ---------------- helpers ----------------
__device__ __forceinline__ uint32_t smem_u32(const void* p) {
    uint32_t a;
    asm("{ .reg .u64 t; cvta.to.shared.u64 t, %1; cvt.u32.u64 %0, t; }" : "=r"(a) : "l"(p));
    return a;
}
__device__ __forceinline__ float tf32f(float x) {
    uint32_t u;
    asm("cvt.rna.tf32.f32 %0, %1;" : "=r"(u) : "f"(x));
    return __uint_as_float(u);
}
__device__ __forceinline__ uint32_t bf2pack(float lo, float hi) {
    uint32_t r;
    asm("cvt.rn.bf16x2.f32 %0, %1, %2;" : "=r"(r) : "f"(hi), "f"(lo));
    return r;
}
__device__ __forceinline__ float bfh(float x) {
    return __bfloat162float(__float2bfloat16(x));
}
__device__ __forceinline__ void mma_tf32(float* c, uint32_t a0, uint32_t a1,
                                         uint32_t a2, uint32_t a3,
                                         uint32_t b0, uint32_t b1) {
    asm volatile(
        "mma.sync.aligned.m16n8k8.row.col.f32.tf32.tf32.f32 "
        "{%0,%1,%2,%3},{%4,%5,%6,%7},{%8,%9},{%0,%1,%2,%3};"
        : "+f"(c[0]), "+f"(c[1]), "+f"(c[2]), "+f"(c[3])
        : "r"(a0), "r"(a1), "r"(a2), "r"(a3), "r"(b0), "r"(b1));
}
__device__ __forceinline__ void mma_bf16(float* c, const uint32_t* a,
                                         uint32_t b0, uint32_t b1) {
    asm volatile(
        "mma.sync.aligned.m16n8k16.row.col.f32.bf16.bf16.f32 "
        "{%0,%1,%2,%3},{%4,%5,%6,%7},{%8,%9},{%0,%1,%2,%3};"
        : "+f"(c[0]), "+f"(c[1]), "+f"(c[2]), "+f"(c[3])
        : "r"(a[0]), "r"(a[1]), "r"(a[2]), "r"(a[3]), "r"(b0), "r"(b1));
}
__device__ __forceinline__ void ldsm4(uint32_t* r, uint32_t addr) {
    asm volatile("ldmatrix.sync.aligned.m8n8.x4.shared.b16 {%0,%1,%2,%3},[%4];"
                 : "=r"(r[0]), "=r"(r[1]), "=r"(r[2]), "=r"(r[3]) : "r"(addr));
}

// ---------------- projection kernel ----------------
__global__ void __launch_bounds__(256) proj_kernel(
    const float* __restrict__ x,
    const float* __restrict__ wq, const float* __restrict__ bq,
    const float* __restrict__ wk, const float* __restrict__ bk,
    const float* __restrict__ wv, const float* __restrict__ bv)
{
    __shared__ float xs[32][256];
    __shared__ float ws[32][33];

    const int b  = blockIdx.z;
    const int n0 = blockIdx.x * 256;
    const int o0 = blockIdx.y * 32;
    const int tid = threadIdx.x;
    const int tx = tid & 63;
    const int ty = tid >> 6;

    float acc[8][4];
#pragma unroll
    for (int i = 0; i < 8; i++)
#pragma unroll
        for (int k = 0; k < 4; k++) acc[i][k] = 0.f;

    for (int cc = 0; cc < NC; cc += 32) {
        __syncthreads();
#pragma unroll
        for (int p = 0; p < 8; p++) {
            int idx = tid + p * 256;
            int c  = idx >> 6;
            int n4 = idx & 63;
            *(float4*)&xs[c][n4 * 4] =
                *(const float4*)&x[(size_t)(b * NC + cc + c) * NN + n0 + n4 * 4];
        }
#pragma unroll
        for (int p = 0; p < 4; p++) {
            int idx = tid + p * 256;
            int o  = idx >> 5;
            int c2 = idx & 31;
            int og = o0 + o;
            const float* wsrc;
            if (og < 32)        wsrc = wq + og * NC;
            else if (og < 64)   wsrc = wk + (og - 32) * NC;
            else                wsrc = wv + (og - 64) * NC;
            ws[o][c2] = wsrc[cc + c2];
        }
        __syncthreads();
#pragma unroll
        for (int c = 0; c < 32; c++) {
            float4 xv = *(const float4*)&xs[c][tx * 4];
#pragma unroll
            for (int i = 0; i < 8; i++) {
                float wv_ = ws[ty * 8 + i][c];
                acc[i][0] = fmaf(wv_, xv.x, acc[i][0]);
                acc[i][1] = fmaf(wv_, xv.y, acc[i][1]);
                acc[i][2] = fmaf(wv_, xv.z, acc[i][2]);
                acc[i][3] = fmaf(wv_, xv.w, acc[i][3]);
            }
        }
    }

#pragma unroll
    for (int i = 0; i < 8; i++) {
        int og = o0 + ty * 8 + i;
        if (og < 32) {
            float bias = bq[og];
            float4 v4 = make_float4(acc[i][0]+bias, acc[i][1]+bias, acc[i][2]+bias, acc[i][3]+bias);
            *(float4*)&g_q[((size_t)b * NCQ + og) * NN + n0 + tx * 4] = v4;
        } else if (og < 64) {
            float bias = bk[og - 32];
            float4 v4 = make_float4(acc[i][0]+bias, acc[i][1]+bias, acc[i][2]+bias, acc[i][3]+bias);
            *(float4*)&g_k[((size_t)b * NCQ + (og - 32)) * NN + n0 + tx * 4] = v4;
        } else {
            int ch = og - 64;
            float bias = bv[ch];
            float vals[4] = {acc[i][0]+bias, acc[i][1]+bias, acc[i][2]+bias, acc[i][3]+bias};
            uint32_t hp[2], lp[2];
#pragma unroll
            for (int p = 0; p < 2; p++) {
                float h0 = bfh(vals[2*p]), h1 = bfh(vals[2*p+1]);
                hp[p] = bf2pack(h0, h1);
                lp[p] = bf2pack(vals[2*p] - h0, vals[2*p+1] - h1);
            }
            size_t off = ((size_t)b * NC + ch) * NN + n0 + tx * 4;
            *(uint32_t*)&vv_h[off]     = hp[0];
            *(uint32_t*)&vv_h[off + 2] = hp[1];
            *(uint32_t*)&vv_l[off]     = lp[0];
            *(uint32_t*)&vv_l[off + 2] = lp[1];
        }
    }
}

// ---------------- transpose + tf32 split for Q, K ----------------
__global__ void __launch_bounds__(256) tsplit_kernel()
{
    __shared__ float ts[32][68];
    const int b = blockIdx.z;
    const int which = blockIdx.y;
    const int n0 = blockIdx.x * 64;
    const int tid = threadIdx.x;

    const float* src = which ? g_k : g_q;
    float* dh = which ? kt_h : qt_h;
    float* dl = which ? kt_l : qt_l;

#pragma unroll
    for (int i = 0; i < 2; i++) {
        int idx = tid + i * 256;
        int d  = idx >> 4;
        int n4 = (idx & 15) * 4;
        float4 v = *(const float4*)&src[((size_t)b * 32 + d) * NN + n0 + n4];
        ts[d][n4 + 0] = v.x; ts[d][n4 + 1] = v.y; ts[d][n4 + 2] = v.z; ts[d][n4 + 3] = v.w;
    }
    __syncthreads();
#pragma unroll
    for (int i = 0; i < 2; i++) {
        int idx = tid + i * 256;
        int n  = idx >> 3;
        int c4 = (idx & 7) * 4;
        float x0 = ts[c4+0][n], x1 = ts[c4+1][n], x2 = ts[c4+2][n], x3 = ts[c4+3][n];
        float4 h4 = make_float4(tf32f(x0), tf32f(x1), tf32f(x2), tf32f(x3));
        float4 l4 = make_float4(tf32f(x0-h4.x), tf32f(x1-h4.y), tf32f(x2-h4.z), tf32f(x3-h4.w));
        size_t off = ((size_t)b * NN + n0 + n) * 32 + c4;
        *(float4*)&dh[off] = h4;
        *(float4*)&dl[off] = l4;
    }
}

// ---------------- fused attention kernel (mma.sync, tf32x2 QK + bf16x2 PV) ----
// smem bytes:
//   [0,     18432)  qs  f32 [2 split][64][36]
//   [18432, 36864)  ks  f32 [2 buf][2 split][32][36]
//   [36864, 102400) vs  bf16 [2 buf][2 split][256][32] (16B-block xor swizzle)
#define SM_KS 18432
#define SM_VS 36864
#define SMEM_BYTES 102400

__global__ void __launch_bounds__(256, 2) attn_kernel(float* __restrict__ out,
                                                      const float* __restrict__ gamma)
{
    extern __shared__ char smem[];
    float* qs = (float*)smem;
    float* ks = (float*)(smem + SM_KS);
    __nv_bfloat16* vs = (__nv_bfloat16*)(smem + SM_VS);
    const uint32_t sb = smem_u32(smem);

    const int b    = blockIdx.y;
    const int n0   = blockIdx.x * MR;
    const int tid  = threadIdx.x;
    const int w    = tid >> 5;
    const int lane = tid & 31;
    const int mg   = w >> 1;          // row group 0..3 (16 rows each)
    const int cg   = w & 1;           // channel group 0..1 (128 ch each)
    const int lq   = lane >> 2;       // lane/4
    const int lr   = lane & 3;        // lane%4

    // ---- load Q tiles (both splits) ----
#pragma unroll
    for (int s = 0; s < 2; s++) {
        const float* src = s ? qt_l : qt_h;
#pragma unroll
        for (int i = 0; i < 2; i++) {
            int idx = tid + i * 256;
            int row = idx >> 3, d4 = (idx & 7) * 4;
            *(float4*)&qs[s * 2304 + row * 36 + d4] =
                *(const float4*)&src[((size_t)b * NN + n0 + row) * 32 + d4];
        }
    }

    // ---- tile load helper (as lambda-ish macro) ----
#define LOAD_TILE(BUF, M1) do { \
    int key = tid >> 3, d4 = (tid & 7) * 4; \
    *(float4*)&ks[((BUF)*2 + 0) * 1152 + key * 36 + d4] = \
        *(const float4*)&kt_h[((size_t)b * NN + (M1) + key) * 32 + d4]; \
    *(float4*)&ks[((BUF)*2 + 1) * 1152 + key * 36 + d4] = \
        *(const float4*)&kt_l[((size_t)b * NN + (M1) + key) * 32 + d4]; \
    _Pragma("unroll") \
    for (int i = 0; i < 4; i++) { \
        int idx = tid + i * 256; \
        int ch = idx >> 2, kq = idx & 3; \
        int kqs = kq ^ (ch & 3); \
        *(float4*)&vs[((BUF)*2 + 0) * 8192 + ch * 32 + kqs * 8] = \
            *(const float4*)&vv_h[((size_t)b * NC + ch) * NN + (M1) + kq * 8]; \
        *(float4*)&vs[((BUF)*2 + 1) * 8192 + ch * 32 + kqs * 8] = \
            *(const float4*)&vv_l[((size_t)b * NC + ch) * NN + (M1) + kq * 8]; \
    } \
} while (0)

    LOAD_TILE(0, 0);

    float O[16][4];
#pragma unroll
    for (int i = 0; i < 16; i++)
#pragma unroll
        for (int j = 0; j < 4; j++) O[i][j] = 0.f;
    float lsum0 = 0.f, lsum1 = 0.f;

    const int g  = lane >> 3;        // ldmatrix group
    const int gr = lane & 7;

    __syncthreads();

    for (int t = 0; t < NN / TK; t++) {
        const int buf = t & 1;
        if (t + 1 < NN / TK) LOAD_TILE(buf ^ 1, (t + 1) * TK);

#pragma unroll
        for (int h = 0; h < 2; h++) {          // two 16-key halves
            const int k0 = h * 16;

            // ---- QK: tf32x2 (hh, hl, lh) ----
            float e0[4] = {0,0,0,0}, e1[4] = {0,0,0,0};
#pragma unroll
            for (int s = 0; s < 3; s++) {
                const float* qsrc = qs + (s == 2 ? 2304 : 0);
                const float* kb   = ks + (buf * 2 + (s == 1 ? 1 : 0)) * 1152;
#pragma unroll
                for (int kc = 0; kc < 4; kc++) {
                    int c = kc * 8 + lr;
                    uint32_t a0 = __float_as_uint(qsrc[(mg*16 + lq    ) * 36 + c    ]);
                    uint32_t a1 = __float_as_uint(qsrc[(mg*16 + lq + 8) * 36 + c    ]);
                    uint32_t a2 = __float_as_uint(qsrc[(mg*16 + lq    ) * 36 + c + 4]);
                    uint32_t a3 = __float_as_uint(qsrc[(mg*16 + lq + 8) * 36 + c + 4]);
                    uint32_t b0 = __float_as_uint(kb[(k0     + lq) * 36 + kc*8 + lr    ]);
                    uint32_t b1 = __float_as_uint(kb[(k0     + lq) * 36 + kc*8 + lr + 4]);
                    mma_tf32(e0, a0, a1, a2, a3, b0, b1);
                    uint32_t b2 = __float_as_uint(kb[(k0 + 8 + lq) * 36 + kc*8 + lr    ]);
                    uint32_t b3 = __float_as_uint(kb[(k0 + 8 + lq) * 36 + kc*8 + lr + 4]);
                    mma_tf32(e1, a0, a1, a2, a3, b2, b3);
                }
            }

            // ---- softmax numerators + bf16 split P fragments ----
            float p00 = __expf(e0[0]), p01 = __expf(e0[1]);
            float p02 = __expf(e0[2]), p03 = __expf(e0[3]);
            float p10 = __expf(e1[0]), p11 = __expf(e1[1]);
            float p12 = __expf(e1[2]), p13 = __expf(e1[3]);
            lsum0 += p00 + p01 + p10 + p11;
            lsum1 += p02 + p03 + p12 + p13;

            uint32_t PH[4], PL[4];
            {
                float h0, h1;
                h0 = bfh(p00); h1 = bfh(p01);
                PH[0] = bf2pack(h0, h1); PL[0] = bf2pack(p00 - h0, p01 - h1);
                h0 = bfh(p02); h1 = bfh(p03);
                PH[1] = bf2pack(h0, h1); PL[1] = bf2pack(p02 - h0, p03 - h1);
                h0 = bfh(p10); h1 = bfh(p11);
                PH[2] = bf2pack(h0, h1); PL[2] = bf2pack(p10 - h0, p11 - h1);
                h0 = bfh(p12); h1 = bfh(p13);
                PH[3] = bf2pack(h0, h1); PL[3] = bf2pack(p12 - h0, p13 - h1);
            }

            // ---- PV: bf16x2 over 128 channels (8 pairs of n8 chunks) ----
            const int chL  = cg * 128 + ((g >> 1) << 3) + gr;   // + np*16
            const int kblk = h * 2 + (g & 1);
#pragma unroll
            for (int np = 0; np < 8; np++) {
                int ch = chL + np * 16;
                uint32_t row_off = (uint32_t)(ch * 64 + ((kblk ^ (ch & 3)) * 16));
                uint32_t ah = sb + SM_VS + (buf * 2 + 0) * 16384 + row_off;
                uint32_t al = sb + SM_VS + (buf * 2 + 1) * 16384 + row_off;
                uint32_t vh[4], vl[4];
                ldsm4(vh, ah);
                ldsm4(vl, al);
#pragma unroll
                for (int u = 0; u < 2; u++) {
                    float* o = O[np * 2 + u];
                    mma_bf16(o, PH, vh[2*u], vh[2*u + 1]);
                    mma_bf16(o, PH, vl[2*u], vl[2*u + 1]);
                    mma_bf16(o, PL, vh[2*u], vh[2*u + 1]);
                }
            }
        }
        __syncthreads();
    }

    // ---- row-sum reduce over lane quads ----
    lsum0 += __shfl_xor_sync(0xffffffffu, lsum0, 1);
    lsum0 += __shfl_xor_sync(0xffffffffu, lsum0, 2);
    lsum1 += __shfl_xor_sync(0xffffffffu, lsum1, 1);
    lsum1 += __shfl_xor_sync(0xffffffffu, lsum1, 2);
    const float inv0 = 1.0f / lsum0;
    const float inv1 = 1.0f / lsum1;
    const float gm = __ldg(gamma);

    // ---- epilogue: quantize into smem staging [256 ch][68], then coalesced store
    float* stg = (float*)smem;
    __syncthreads();
#pragma unroll
    for (int oc = 0; oc < 16; oc++) {
        int ch = cg * 128 + oc * 8 + lr * 2;
        int r0 = mg * 16 + lq, r1 = r0 + 8;
        float o0 = O[oc][0] * inv0, o1 = O[oc][1] * inv0;
        float o2 = O[oc][2] * inv1, o3 = O[oc][3] * inv1;
        stg[ ch      * 68 + r0] = floorf((gm * o0 + o0) * 256.f) * 0.00390625f;
        stg[(ch + 1) * 68 + r0] = floorf((gm * o1 + o1) * 256.f) * 0.00390625f;
        stg[ ch      * 68 + r1] = floorf((gm * o2 + o2) * 256.f) * 0.00390625f;
        stg[(ch + 1) * 68 + r1] = floorf((gm * o3 + o3) * 256.f) * 0.00390625f;
    }
    __syncthreads();
#pragma unroll
    for (int i = 0; i < 16; i++) {
        int ch = (tid >> 4) + i * 16;
        int r4 = (tid & 15) * 4;
        *(float4*)&out[((size_t)b * NC + ch) * NN + n0 + r4] = *(float4*)&stg[ch * 68 + r4];
    }
}

// ---------------- launch ----------------
extern "C" void kernel_launch(void* const* d_in, const int* in_sizes, int n_in,
                              void* d_out, int out_size)
{
    const float* x     = (const float*)d_in[0];
    const float* wq    = (const float*)d_in[1];
    const float* bq    = (const float*)d_in[2];
    const float* wk    = (const float*)d_in[3];
    const float* bk    = (const float*)d_in[4];
    const float* wv    = (const float*)d_in[5];
    const float* bv    = (const float*)d_in[6];
    const float* gamma = (const float*)d_in[7];
    float* out = (float*)d_out;

    dim3 gp(NN / 256, 10, NB);
    proj_kernel<<<gp, 256>>>(x, wq, bq, wk, bk, wv, bv);

    dim3 gt(NN / 64, 2, NB);
    tsplit_kernel<<<gt, 256>>>();

    cudaFuncSetAttribute(attn_kernel, cudaFuncAttributeMaxDynamicSharedMemorySize, SMEM_BYTES);
    dim3 ga(NN / MR, NB);
    attn_kernel<<<ga, 256, SMEM_BYTES>>>(out, gamma);
}

// round 9
// speedup vs baseline: 2.0348x; 1.0085x over previous
#include <cuda_runtime.h>
#include <cuda_bf16.h>
#include <cstdint>

#define NB  8
#define NC  256
#define NCQ 32
#define NN  4096
#define MR  64      // query rows per CTA
#define TK  32      // keys per gmem tile

// ---------------- scratch (no allocs allowed) ----------------
__device__ float g_q[NB * NCQ * NN];            // [b][d][n]
__device__ float g_k[NB * NCQ * NN];            // [b][d][n]
__device__ float qt_h[NB * NN * NCQ];           // [b][n][d] tf32-rounded
__device__ float qt_l[NB * NN * NCQ];           // residual (tf32-rounded)
__device__ float kt_h[NB * NN * NCQ];
__device__ float kt_l[NB * NN * NCQ];
__device__ __nv_bfloat16 vv_h[NB * NC * NN];    // [b][ch][n] bf16-hi
__device__ __nv_bfloat16 vv_l[NB * NC * NN];    // bf16 residual

// ---------------- helpers ----------------
__device__ __forceinline__ uint32_t smem_u32(const void* p) {
    uint32_t a;
    asm("{ .reg .u64 t; cvta.to.shared.u64 t, %1; cvt.u32.u64 %0, t; }" : "=r"(a) : "l"(p));
    return a;
}
__device__ __forceinline__ float tf32f(float x) {
    uint32_t u;
    asm("cvt.rna.tf32.f32 %0, %1;" : "=r"(u) : "f"(x));
    return __uint_as_float(u);
}
__device__ __forceinline__ uint32_t bf2pack(float lo, float hi) {
    uint32_t r;
    asm("cvt.rn.bf16x2.f32 %0, %1, %2;" : "=r"(r) : "f"(hi), "f"(lo));
    return r;
}
__device__ __forceinline__ float bfh(float x) {
    return __bfloat162float(__float2bfloat16(x));
}
__device__ __forceinline__ unsigned long long pack2(float a, float b) {
    unsigned long long r;
    asm("mov.b64 %0, {%1, %2};" : "=l"(r) : "f"(a), "f"(b));
    return r;
}
__device__ __forceinline__ void fma2(unsigned long long& d, unsigned long long a, unsigned long long b) {
    asm("fma.rn.f32x2 %0, %1, %2, %0;" : "+l"(d) : "l"(a), "l"(b));
}
__device__ __forceinline__ float2 unpack2(unsigned long long v) {
    float lo, hi;
    asm("mov.b64 {%0, %1}, %2;" : "=f"(lo), "=f"(hi) : "l"(v));
    return make_float2(lo, hi);
}
__device__ __forceinline__ void mma_tf32(float* c, uint32_t a0, uint32_t a1,
                                         uint32_t a2, uint32_t a3,
                                         uint32_t b0, uint32_t b1) {
    asm volatile(
        "mma.sync.aligned.m16n8k8.row.col.f32.tf32.tf32.f32 "
        "{%0,%1,%2,%3},{%4,%5,%6,%7},{%8,%9},{%0,%1,%2,%3};"
        : "+f"(c[0]), "+f"(c[1]), "+f"(c[2]), "+f"(c[3])
        : "r"(a0), "r"(a1), "r"(a2), "r"(a3), "r"(b0), "r"(b1));
}
__device__ __forceinline__ void mma_bf16(float* c, const uint32_t* a,
                                         uint32_t b0, uint32_t b1) {
    asm volatile(
        "mma.sync.aligned.m16n8k16.row.col.f32.bf16.bf16.f32 "
        "{%0,%1,%2,%3},{%4,%5,%6,%7},{%8,%9},{%0,%1,%2,%3};"
        : "+f"(c[0]), "+f"(c[1]), "+f"(c[2]), "+f"(c[3])
        : "r"(a[0]), "r"(a[1]), "r"(a[2]), "r"(a[3]), "r"(b0), "r"(b1));
}
// R4's validated helper: NON-trans ldmatrix (this was the R5-R8 regression).
__device__ __forceinline__ void ldsm4(uint32_t* r, uint32_t addr) {
    asm volatile("ldmatrix.sync.aligned.m8n8.x4.shared.b16 {%0,%1,%2,%3},[%4];"
                 : "=r"(r[0]), "=r"(r[1]), "=r"(r[2]), "=r"(r[3]) : "r"(addr));
}

// ---------------- projection kernel (R4 structure, f32x2 inner loop) --------
__global__ void __launch_bounds__(256) proj_kernel(
    const float* __restrict__ x,
    const float* __restrict__ wq, const float* __restrict__ bq,
    const float* __restrict__ wk, const float* __restrict__ bk,
    const float* __restrict__ wv, const float* __restrict__ bv)
{
    __shared__ float xs[32][256];
    __shared__ float ws[32][33];

    const int b  = blockIdx.z;
    const int n0 = blockIdx.x * 256;
    const int o0 = blockIdx.y * 32;
    const int tid = threadIdx.x;
    const int tx = tid & 63;
    const int ty = tid >> 6;

    unsigned long long accp[8][2];
#pragma unroll
    for (int i = 0; i < 8; i++) { accp[i][0] = 0ull; accp[i][1] = 0ull; }

    for (int cc = 0; cc < NC; cc += 32) {
        __syncthreads();
#pragma unroll
        for (int p = 0; p < 8; p++) {
            int idx = tid + p * 256;
            int c  = idx >> 6;
            int n4 = idx & 63;
            *(float4*)&xs[c][n4 * 4] =
                *(const float4*)&x[(size_t)(b * NC + cc + c) * NN + n0 + n4 * 4];
        }
#pragma unroll
        for (int p = 0; p < 4; p++) {
            int idx = tid + p * 256;
            int o  = idx >> 5;
            int c2 = idx & 31;
            int og = o0 + o;
            const float* wsrc;
            if (og < 32)        wsrc = wq + og * NC;
            else if (og < 64)   wsrc = wk + (og - 32) * NC;
            else                wsrc = wv + (og - 64) * NC;
            ws[o][c2] = wsrc[cc + c2];
        }
        __syncthreads();
#pragma unroll
        for (int c = 0; c < 32; c++) {
            ulonglong2 xp = *(const ulonglong2*)&xs[c][tx * 4];
#pragma unroll
            for (int i = 0; i < 8; i++) {
                float wv_ = ws[ty * 8 + i][c];
                unsigned long long w2 = pack2(wv_, wv_);
                fma2(accp[i][0], w2, xp.x);
                fma2(accp[i][1], w2, xp.y);
            }
        }
    }

    float acc[8][4];
#pragma unroll
    for (int i = 0; i < 8; i++) {
        float2 f0 = unpack2(accp[i][0]);
        float2 f1 = unpack2(accp[i][1]);
        acc[i][0] = f0.x; acc[i][1] = f0.y; acc[i][2] = f1.x; acc[i][3] = f1.y;
    }

#pragma unroll
    for (int i = 0; i < 8; i++) {
        int og = o0 + ty * 8 + i;
        if (og < 32) {
            float bias = bq[og];
            float4 v4 = make_float4(acc[i][0]+bias, acc[i][1]+bias, acc[i][2]+bias, acc[i][3]+bias);
            *(float4*)&g_q[((size_t)b * NCQ + og) * NN + n0 + tx * 4] = v4;
        } else if (og < 64) {
            float bias = bk[og - 32];
            float4 v4 = make_float4(acc[i][0]+bias, acc[i][1]+bias, acc[i][2]+bias, acc[i][3]+bias);
            *(float4*)&g_k[((size_t)b * NCQ + (og - 32)) * NN + n0 + tx * 4] = v4;
        } else {
            int ch = og - 64;
            float bias = bv[ch];
            float vals[4] = {acc[i][0]+bias, acc[i][1]+bias, acc[i][2]+bias, acc[i][3]+bias};
            uint32_t hp[2], lp[2];
#pragma unroll
            for (int p = 0; p < 2; p++) {
                float h0 = bfh(vals[2*p]), h1 = bfh(vals[2*p+1]);
                hp[p] = bf2pack(h0, h1);
                lp[p] = bf2pack(vals[2*p] - h0, vals[2*p+1] - h1);
            }
            size_t off = ((size_t)b * NC + ch) * NN + n0 + tx * 4;
            *(uint32_t*)&vv_h[off]     = hp[0];
            *(uint32_t*)&vv_h[off + 2] = hp[1];
            *(uint32_t*)&vv_l[off]     = lp[0];
            *(uint32_t*)&vv_l[off + 2] = lp[1];
        }
    }
}

// ---------------- transpose + tf32 split for Q, K ----------------
__global__ void __launch_bounds__(256) tsplit_kernel()
{
    __shared__ float ts[32][68];
    const int b = blockIdx.z;
    const int which = blockIdx.y;
    const int n0 = blockIdx.x * 64;
    const int tid = threadIdx.x;

    const float* src = which ? g_k : g_q;
    float* dh = which ? kt_h : qt_h;
    float* dl = which ? kt_l : qt_l;

#pragma unroll
    for (int i = 0; i < 2; i++) {
        int idx = tid + i * 256;
        int d  = idx >> 4;
        int n4 = (idx & 15) * 4;
        float4 v = *(const float4*)&src[((size_t)b * 32 + d) * NN + n0 + n4];
        ts[d][n4 + 0] = v.x; ts[d][n4 + 1] = v.y; ts[d][n4 + 2] = v.z; ts[d][n4 + 3] = v.w;
    }
    __syncthreads();
#pragma unroll
    for (int i = 0; i < 2; i++) {
        int idx = tid + i * 256;
        int n  = idx >> 3;
        int c4 = (idx & 7) * 4;
        float x0 = ts[c4+0][n], x1 = ts[c4+1][n], x2 = ts[c4+2][n], x3 = ts[c4+3][n];
        float4 h4 = make_float4(tf32f(x0), tf32f(x1), tf32f(x2), tf32f(x3));
        float4 l4 = make_float4(tf32f(x0-h4.x), tf32f(x1-h4.y), tf32f(x2-h4.z), tf32f(x3-h4.w));
        size_t off = ((size_t)b * NN + n0 + n) * 32 + c4;
        *(float4*)&dh[off] = h4;
        *(float4*)&dl[off] = l4;
    }
}

// ---------------- fused attention kernel (R4, unchanged) --------------------
// smem bytes:
//   [0,     18432)  qs  f32 [2 split][64][36]
//   [18432, 36864)  ks  f32 [2 buf][2 split][32][36]
//   [36864, 102400) vs  bf16 [2 buf][2 split][256][32] (16B-block xor swizzle)
#define SM_KS 18432
#define SM_VS 36864
#define SMEM_BYTES 102400

__global__ void __launch_bounds__(256, 2) attn_kernel(float* __restrict__ out,
                                                      const float* __restrict__ gamma)
{
    extern __shared__ char smem[];
    float* qs = (float*)smem;
    float* ks = (float*)(smem + SM_KS);
    __nv_bfloat16* vs = (__nv_bfloat16*)(smem + SM_VS);
    const uint32_t sb = smem_u32(smem);

    const int b    = blockIdx.y;
    const int n0   = blockIdx.x * MR;
    const int tid  = threadIdx.x;
    const int w    = tid >> 5;
    const int lane = tid & 31;
    const int mg   = w >> 1;          // row group 0..3 (16 rows each)
    const int cg   = w & 1;           // channel group 0..1 (128 ch each)
    const int lq   = lane >> 2;       // lane/4
    const int lr   = lane & 3;        // lane%4

    // ---- load Q tiles (both splits) ----
#pragma unroll
    for (int s = 0; s < 2; s++) {
        const float* src = s ? qt_l : qt_h;
#pragma unroll
        for (int i = 0; i < 2; i++) {
            int idx = tid + i * 256;
            int row = idx >> 3, d4 = (idx & 7) * 4;
            *(float4*)&qs[s * 2304 + row * 36 + d4] =
                *(const float4*)&src[((size_t)b * NN + n0 + row) * 32 + d4];
        }
    }

    // ---- tile load helper ----
#define LOAD_TILE(BUF, M1) do { \
    int key = tid >> 3, d4 = (tid & 7) * 4; \
    *(float4*)&ks[((BUF)*2 + 0) * 1152 + key * 36 + d4] = \
        *(const float4*)&kt_h[((size_t)b * NN + (M1) + key) * 32 + d4]; \
    *(float4*)&ks[((BUF)*2 + 1) * 1152 + key * 36 + d4] = \
        *(const float4*)&kt_l[((size_t)b * NN + (M1) + key) * 32 + d4]; \
    _Pragma("unroll") \
    for (int i = 0; i < 4; i++) { \
        int idx = tid + i * 256; \
        int ch = idx >> 2, kq = idx & 3; \
        int kqs = kq ^ (ch & 3); \
        *(float4*)&vs[((BUF)*2 + 0) * 8192 + ch * 32 + kqs * 8] = \
            *(const float4*)&vv_h[((size_t)b * NC + ch) * NN + (M1) + kq * 8]; \
        *(float4*)&vs[((BUF)*2 + 1) * 8192 + ch * 32 + kqs * 8] = \
            *(const float4*)&vv_l[((size_t)b * NC + ch) * NN + (M1) + kq * 8]; \
    } \
} while (0)

    LOAD_TILE(0, 0);

    float O[16][4];
#pragma unroll
    for (int i = 0; i < 16; i++)
#pragma unroll
        for (int j = 0; j < 4; j++) O[i][j] = 0.f;
    float lsum0 = 0.f, lsum1 = 0.f;

    const int g  = lane >> 3;        // ldmatrix group
    const int gr = lane & 7;

    __syncthreads();

    for (int t = 0; t < NN / TK; t++) {
        const int buf = t & 1;
        if (t + 1 < NN / TK) LOAD_TILE(buf ^ 1, (t + 1) * TK);

#pragma unroll
        for (int h = 0; h < 2; h++) {          // two 16-key halves
            const int k0 = h * 16;

            // ---- QK: tf32x2 (hh, hl, lh) ----
            float e0[4] = {0,0,0,0}, e1[4] = {0,0,0,0};
#pragma unroll
            for (int s = 0; s < 3; s++) {
                const float* qsrc = qs + (s == 2 ? 2304 : 0);
                const float* kb   = ks + (buf * 2 + (s == 1 ? 1 : 0)) * 1152;
#pragma unroll
                for (int kc = 0; kc < 4; kc++) {
                    int c = kc * 8 + lr;
                    uint32_t a0 = __float_as_uint(qsrc[(mg*16 + lq    ) * 36 + c    ]);
                    uint32_t a1 = __float_as_uint(qsrc[(mg*16 + lq + 8) * 36 + c    ]);
                    uint32_t a2 = __float_as_uint(qsrc[(mg*16 + lq    ) * 36 + c + 4]);
                    uint32_t a3 = __float_as_uint(qsrc[(mg*16 + lq + 8) * 36 + c + 4]);
                    uint32_t b0 = __float_as_uint(kb[(k0     + lq) * 36 + kc*8 + lr    ]);
                    uint32_t b1 = __float_as_uint(kb[(k0     + lq) * 36 + kc*8 + lr + 4]);
                    mma_tf32(e0, a0, a1, a2, a3, b0, b1);
                    uint32_t b2 = __float_as_uint(kb[(k0 + 8 + lq) * 36 + kc*8 + lr    ]);
                    uint32_t b3 = __float_as_uint(kb[(k0 + 8 + lq) * 36 + kc*8 + lr + 4]);
                    mma_tf32(e1, a0, a1, a2, a3, b2, b3);
                }
            }

            // ---- softmax numerators + bf16 split P fragments ----
            float p00 = __expf(e0[0]), p01 = __expf(e0[1]);
            float p02 = __expf(e0[2]), p03 = __expf(e0[3]);
            float p10 = __expf(e1[0]), p11 = __expf(e1[1]);
            float p12 = __expf(e1[2]), p13 = __expf(e1[3]);
            lsum0 += p00 + p01 + p10 + p11;
            lsum1 += p02 + p03 + p12 + p13;

            uint32_t PH[4], PL[4];
            {
                float h0, h1;
                h0 = bfh(p00); h1 = bfh(p01);
                PH[0] = bf2pack(h0, h1); PL[0] = bf2pack(p00 - h0, p01 - h1);
                h0 = bfh(p02); h1 = bfh(p03);
                PH[1] = bf2pack(h0, h1); PL[1] = bf2pack(p02 - h0, p03 - h1);
                h0 = bfh(p10); h1 = bfh(p11);
                PH[2] = bf2pack(h0, h1); PL[2] = bf2pack(p10 - h0, p11 - h1);
                h0 = bfh(p12); h1 = bfh(p13);
                PH[3] = bf2pack(h0, h1); PL[3] = bf2pack(p12 - h0, p13 - h1);
            }

            // ---- PV: bf16x2 over 128 channels (8 pairs of n8 chunks) ----
            const int chL  = cg * 128 + ((g >> 1) << 3) + gr;   // + np*16
            const int kblk = h * 2 + (g & 1);
#pragma unroll
            for (int np = 0; np < 8; np++) {
                int ch = chL + np * 16;
                uint32_t row_off = (uint32_t)(ch * 64 + ((kblk ^ (ch & 3)) * 16));
                uint32_t ah = sb + SM_VS + (buf * 2 + 0) * 16384 + row_off;
                uint32_t al = sb + SM_VS + (buf * 2 + 1) * 16384 + row_off;
                uint32_t vh[4], vl[4];
                ldsm4(vh, ah);
                ldsm4(vl, al);
#pragma unroll
                for (int u = 0; u < 2; u++) {
                    float* o = O[np * 2 + u];
                    mma_bf16(o, PH, vh[2*u], vh[2*u + 1]);
                    mma_bf16(o, PH, vl[2*u], vl[2*u + 1]);
                    mma_bf16(o, PL, vh[2*u], vh[2*u + 1]);
                }
            }
        }
        __syncthreads();
    }

    // ---- row-sum reduce over lane quads ----
    lsum0 += __shfl_xor_sync(0xffffffffu, lsum0, 1);
    lsum0 += __shfl_xor_sync(0xffffffffu, lsum0, 2);
    lsum1 += __shfl_xor_sync(0xffffffffu, lsum1, 1);
    lsum1 += __shfl_xor_sync(0xffffffffu, lsum1, 2);
    const float inv0 = 1.0f / lsum0;
    const float inv1 = 1.0f / lsum1;
    const float gm = __ldg(gamma);

    // ---- epilogue: quantize into smem staging [256 ch][68], coalesced store ----
    float* stg = (float*)smem;
    __syncthreads();
#pragma unroll
    for (int oc = 0; oc < 16; oc++) {
        int ch = cg * 128 + oc * 8 + lr * 2;
        int r0 = mg * 16 + lq, r1 = r0 + 8;
        float o0 = O[oc][0] * inv0, o1 = O[oc][1] * inv0;
        float o2 = O[oc][2] * inv1, o3 = O[oc][3] * inv1;
        stg[ ch      * 68 + r0] = floorf((gm * o0 + o0) * 256.f) * 0.00390625f;
        stg[(ch + 1) * 68 + r0] = floorf((gm * o1 + o1) * 256.f) * 0.00390625f;
        stg[ ch      * 68 + r1] = floorf((gm * o2 + o2) * 256.f) * 0.00390625f;
        stg[(ch + 1) * 68 + r1] = floorf((gm * o3 + o3) * 256.f) * 0.00390625f;
    }
    __syncthreads();
#pragma unroll
    for (int i = 0; i < 16; i++) {
        int ch = (tid >> 4) + i * 16;
        int r4 = (tid & 15) * 4;
        *(float4*)&out[((size_t)b * NC + ch) * NN + n0 + r4] = *(float4*)&stg[ch * 68 + r4];
    }
}

// ---------------- launch ----------------
extern "C" void kernel_launch(void* const* d_in, const int* in_sizes, int n_in,
                              void* d_out, int out_size)
{
    const float* x     = (const float*)d_in[0];
    const float* wq    = (const float*)d_in[1];
    const float* bq    = (const float*)d_in[2];
    const float* wk    = (const float*)d_in[3];
    const float* bk    = (const float*)d_in[4];
    const float* wv    = (const float*)d_in[5];
    const float* bv    = (const float*)d_in[6];
    const float* gamma = (const float*)d_in[7];
    float* out = (float*)d_out;

    dim3 gp(NN / 256, 10, NB);
    proj_kernel<<<gp, 256>>>(x, wq, bq, wk, bk, wv, bv);

    dim3 gt(NN / 64, 2, NB);
    tsplit_kernel<<<gt, 256>>>();

    cudaFuncSetAttribute(attn_kernel, cudaFuncAttributeMaxDynamicSharedMemorySize, SMEM_BYTES);
    dim3 ga(NN / MR, NB);
    attn_kernel<<<ga, 256, SMEM_BYTES>>>(out, gamma);
}

// round 10
// speedup vs baseline: 2.6973x; 1.3256x over previous
#include <cuda_runtime.h>
#include <cuda_bf16.h>
#include <cstdint>

#define NB  8
#define NC  256
#define NCQ 32
#define NN  4096
#define MR  64      // query rows per CTA
#define TK  32      // keys per gmem tile

// ---------------- scratch (no allocs allowed) ----------------
__device__ float g_q[NB * NCQ * NN];            // [b][d][n]
__device__ float g_k[NB * NCQ * NN];            // [b][d][n]
__device__ alignas(16) __nv_bfloat16 qth[NB * NN * 32];  // [b][n][d] bf16 hi
__device__ alignas(16) __nv_bfloat16 qtl[NB * NN * 32];  // residual
__device__ alignas(16) __nv_bfloat16 kth[NB * NN * 32];
__device__ alignas(16) __nv_bfloat16 ktl[NB * NN * 32];
__device__ __nv_bfloat16 vv_h[NB * NC * NN];    // [b][ch][n] bf16-hi
__device__ __nv_bfloat16 vv_l[NB * NC * NN];    // bf16 residual

// ---------------- helpers ----------------
__device__ __forceinline__ uint32_t smem_u32(const void* p) {
    uint32_t a;
    asm("{ .reg .u64 t; cvta.to.shared.u64 t, %1; cvt.u32.u64 %0, t; }" : "=r"(a) : "l"(p));
    return a;
}
__device__ __forceinline__ uint32_t bf2pack(float lo, float hi) {
    uint32_t r;
    asm("cvt.rn.bf16x2.f32 %0, %1, %2;" : "=r"(r) : "f"(hi), "f"(lo));
    return r;
}
__device__ __forceinline__ float bfh(float x) {
    return __bfloat162float(__float2bfloat16(x));
}
__device__ __forceinline__ unsigned long long pack2(float a, float b) {
    unsigned long long r;
    asm("mov.b64 %0, {%1, %2};" : "=l"(r) : "f"(a), "f"(b));
    return r;
}
__device__ __forceinline__ void fma2(unsigned long long& d, unsigned long long a, unsigned long long b) {
    asm("fma.rn.f32x2 %0, %1, %2, %0;" : "+l"(d) : "l"(a), "l"(b));
}
__device__ __forceinline__ float2 unpack2(unsigned long long v) {
    float lo, hi;
    asm("mov.b64 {%0, %1}, %2;" : "=f"(lo), "=f"(hi) : "l"(v));
    return make_float2(lo, hi);
}
__device__ __forceinline__ void mma_bf16(float* c, const uint32_t* a,
                                         uint32_t b0, uint32_t b1) {
    asm volatile(
        "mma.sync.aligned.m16n8k16.row.col.f32.bf16.bf16.f32 "
        "{%0,%1,%2,%3},{%4,%5,%6,%7},{%8,%9},{%0,%1,%2,%3};"
        : "+f"(c[0]), "+f"(c[1]), "+f"(c[2]), "+f"(c[3])
        : "r"(a[0]), "r"(a[1]), "r"(a[2]), "r"(a[3]), "r"(b0), "r"(b1));
}
// R4/R9-validated helper: NON-trans ldmatrix.
__device__ __forceinline__ void ldsm4(uint32_t* r, uint32_t addr) {
    asm volatile("ldmatrix.sync.aligned.m8n8.x4.shared.b16 {%0,%1,%2,%3},[%4];"
                 : "=r"(r[0]), "=r"(r[1]), "=r"(r[2]), "=r"(r[3]) : "r"(addr));
}

// ---------------- projection kernel (byte-identical to R9) ------------------
__global__ void __launch_bounds__(256) proj_kernel(
    const float* __restrict__ x,
    const float* __restrict__ wq, const float* __restrict__ bq,
    const float* __restrict__ wk, const float* __restrict__ bk,
    const float* __restrict__ wv, const float* __restrict__ bv)
{
    __shared__ float xs[32][256];
    __shared__ float ws[32][33];

    const int b  = blockIdx.z;
    const int n0 = blockIdx.x * 256;
    const int o0 = blockIdx.y * 32;
    const int tid = threadIdx.x;
    const int tx = tid & 63;
    const int ty = tid >> 6;

    unsigned long long accp[8][2];
#pragma unroll
    for (int i = 0; i < 8; i++) { accp[i][0] = 0ull; accp[i][1] = 0ull; }

    for (int cc = 0; cc < NC; cc += 32) {
        __syncthreads();
#pragma unroll
        for (int p = 0; p < 8; p++) {
            int idx = tid + p * 256;
            int c  = idx >> 6;
            int n4 = idx & 63;
            *(float4*)&xs[c][n4 * 4] =
                *(const float4*)&x[(size_t)(b * NC + cc + c) * NN + n0 + n4 * 4];
        }
#pragma unroll
        for (int p = 0; p < 4; p++) {
            int idx = tid + p * 256;
            int o  = idx >> 5;
            int c2 = idx & 31;
            int og = o0 + o;
            const float* wsrc;
            if (og < 32)        wsrc = wq + og * NC;
            else if (og < 64)   wsrc = wk + (og - 32) * NC;
            else                wsrc = wv + (og - 64) * NC;
            ws[o][c2] = wsrc[cc + c2];
        }
        __syncthreads();
#pragma unroll
        for (int c = 0; c < 32; c++) {
            ulonglong2 xp = *(const ulonglong2*)&xs[c][tx * 4];
#pragma unroll
            for (int i = 0; i < 8; i++) {
                float wv_ = ws[ty * 8 + i][c];
                unsigned long long w2 = pack2(wv_, wv_);
                fma2(accp[i][0], w2, xp.x);
                fma2(accp[i][1], w2, xp.y);
            }
        }
    }

    float acc[8][4];
#pragma unroll
    for (int i = 0; i < 8; i++) {
        float2 f0 = unpack2(accp[i][0]);
        float2 f1 = unpack2(accp[i][1]);
        acc[i][0] = f0.x; acc[i][1] = f0.y; acc[i][2] = f1.x; acc[i][3] = f1.y;
    }

#pragma unroll
    for (int i = 0; i < 8; i++) {
        int og = o0 + ty * 8 + i;
        if (og < 32) {
            float bias = bq[og];
            float4 v4 = make_float4(acc[i][0]+bias, acc[i][1]+bias, acc[i][2]+bias, acc[i][3]+bias);
            *(float4*)&g_q[((size_t)b * NCQ + og) * NN + n0 + tx * 4] = v4;
        } else if (og < 64) {
            float bias = bk[og - 32];
            float4 v4 = make_float4(acc[i][0]+bias, acc[i][1]+bias, acc[i][2]+bias, acc[i][3]+bias);
            *(float4*)&g_k[((size_t)b * NCQ + (og - 32)) * NN + n0 + tx * 4] = v4;
        } else {
            int ch = og - 64;
            float bias = bv[ch];
            float vals[4] = {acc[i][0]+bias, acc[i][1]+bias, acc[i][2]+bias, acc[i][3]+bias};
            uint32_t hp[2], lp[2];
#pragma unroll
            for (int p = 0; p < 2; p++) {
                float h0 = bfh(vals[2*p]), h1 = bfh(vals[2*p+1]);
                hp[p] = bf2pack(h0, h1);
                lp[p] = bf2pack(vals[2*p] - h0, vals[2*p+1] - h1);
            }
            size_t off = ((size_t)b * NC + ch) * NN + n0 + tx * 4;
            *(uint32_t*)&vv_h[off]     = hp[0];
            *(uint32_t*)&vv_h[off + 2] = hp[1];
            *(uint32_t*)&vv_l[off]     = lp[0];
            *(uint32_t*)&vv_l[off + 2] = lp[1];
        }
    }
}

// ---------------- transpose + bf16-limb split for Q, K ----------------------
// Same indexing as R9's tsplit; only the output format changed (bf16 limbs).
__global__ void __launch_bounds__(256) tsplit_kernel()
{
    __shared__ float ts[32][68];
    const int b = blockIdx.z;
    const int which = blockIdx.y;
    const int n0 = blockIdx.x * 64;
    const int tid = threadIdx.x;

    const float* src = which ? g_k : g_q;
    __nv_bfloat16* dh = which ? kth : qth;
    __nv_bfloat16* dl = which ? ktl : qtl;

#pragma unroll
    for (int i = 0; i < 2; i++) {
        int idx = tid + i * 256;
        int d  = idx >> 4;
        int n4 = (idx & 15) * 4;
        float4 v = *(const float4*)&src[((size_t)b * 32 + d) * NN + n0 + n4];
        ts[d][n4 + 0] = v.x; ts[d][n4 + 1] = v.y; ts[d][n4 + 2] = v.z; ts[d][n4 + 3] = v.w;
    }
    __syncthreads();
#pragma unroll
    for (int i = 0; i < 2; i++) {
        int idx = tid + i * 256;
        int n  = idx >> 3;
        int c4 = (idx & 7) * 4;
        float x0 = ts[c4+0][n], x1 = ts[c4+1][n], x2 = ts[c4+2][n], x3 = ts[c4+3][n];
        float h0 = bfh(x0), h1 = bfh(x1), h2 = bfh(x2), h3 = bfh(x3);
        uint2 hh = make_uint2(bf2pack(h0, h1), bf2pack(h2, h3));
        uint2 ll = make_uint2(bf2pack(x0 - h0, x1 - h1), bf2pack(x2 - h2, x3 - h3));
        size_t off = ((size_t)b * NN + n0 + n) * 32 + c4;
        *(uint2*)&dh[off] = hh;
        *(uint2*)&dl[off] = ll;
    }
}

// ---------------- fused attention kernel (bf16-limb QK + R9 PV) -------------
// smem bytes:
//   [0,     10240)  Q stage  bf16 [2 limb][64 rows][40] (80B row stride)
//   [10240, 20480)  K tiles  bf16 [2 buf][2 limb][32 keys][40]
//   [20480, 86016)  V tiles  bf16 [2 buf][2 limb][256 ch][32] (R9 layout)
//   epilogue staging [256][68] f32 reuses [0, 69632)
#define QS_OFF 0
#define KS_OFF 10240
#define VS_OFF 20480
#define SMEM_BYTES 86016

__global__ void __launch_bounds__(256, 2) attn_kernel(float* __restrict__ out,
                                                      const float* __restrict__ gamma)
{
    extern __shared__ char smem[];
    __nv_bfloat16* vs = (__nv_bfloat16*)(smem + VS_OFF);
    const uint32_t sb = smem_u32(smem);

    const int b    = blockIdx.y;
    const int n0   = blockIdx.x * MR;
    const int tid  = threadIdx.x;
    const int w    = tid >> 5;
    const int lane = tid & 31;
    const int mg   = w >> 1;          // row group 0..3 (16 rows each)
    const int cg   = w & 1;           // channel group 0..1 (128 ch each)
    const int lq   = lane >> 2;       // lane/4
    const int lr   = lane & 3;        // lane%4
    const int g    = lane >> 3;       // ldmatrix group
    const int gr   = lane & 7;

    // ---- stage Q (both limbs) ----
    {
        int row = tid >> 2, seg = tid & 3;
        size_t go = ((size_t)b * NN + n0 + row) * 32 + seg * 8;
        *(uint4*)(smem + QS_OFF +        row * 80 + seg * 16) = *(const uint4*)&qth[go];
        *(uint4*)(smem + QS_OFF + 5120 + row * 80 + seg * 16) = *(const uint4*)&qtl[go];
    }

    // ---- tile load helper: K bf16 limbs + V exactly as R9 ----
#define LOAD_TILE(BUF, M1) do { \
    int key = tid >> 3, dseg = tid & 7; \
    size_t kgo = ((size_t)b * NN + (M1) + key) * 32 + dseg * 4; \
    *(uint2*)(smem + KS_OFF + (BUF) * 5120 +        key * 80 + dseg * 8) = \
        *(const uint2*)&kth[kgo]; \
    *(uint2*)(smem + KS_OFF + (BUF) * 5120 + 2560 + key * 80 + dseg * 8) = \
        *(const uint2*)&ktl[kgo]; \
    _Pragma("unroll") \
    for (int i = 0; i < 4; i++) { \
        int idx = tid + i * 256; \
        int ch = idx >> 2, kq = idx & 3; \
        int kqs = kq ^ (ch & 3); \
        *(float4*)&vs[((BUF)*2 + 0) * 8192 + ch * 32 + kqs * 8] = \
            *(const float4*)&vv_h[((size_t)b * NC + ch) * NN + (M1) + kq * 8]; \
        *(float4*)&vs[((BUF)*2 + 1) * 8192 + ch * 32 + kqs * 8] = \
            *(const float4*)&vv_l[((size_t)b * NC + ch) * NN + (M1) + kq * 8]; \
    } \
} while (0)

    LOAD_TILE(0, 0);
    __syncthreads();

    // ---- hoist Q A-fragments via direct LDS.32 (PTX m16n8k16 A layout:
    //      R0={A[g][2t],A[g][2t+1]}, R1=row+8, R2=k+8, R3=both) ----
    uint32_t QH[2][4], QL[2][4];
    {
        const char* q0 = smem + QS_OFF + (mg * 16 + lq) * 80;
        const char* q8 = q0 + 8 * 80;
#pragma unroll
        for (int ks = 0; ks < 2; ks++) {
            int d0 = (ks * 16 + 2 * lr) * 2;   // byte offset, 4B aligned
            QH[ks][0] = *(const uint32_t*)(q0 + d0);
            QH[ks][1] = *(const uint32_t*)(q8 + d0);
            QH[ks][2] = *(const uint32_t*)(q0 + d0 + 16);
            QH[ks][3] = *(const uint32_t*)(q8 + d0 + 16);
            QL[ks][0] = *(const uint32_t*)(q0 + 5120 + d0);
            QL[ks][1] = *(const uint32_t*)(q8 + 5120 + d0);
            QL[ks][2] = *(const uint32_t*)(q0 + 5120 + d0 + 16);
            QL[ks][3] = *(const uint32_t*)(q8 + 5120 + d0 + 16);
        }
    }

    float O[16][4];
#pragma unroll
    for (int i = 0; i < 16; i++)
#pragma unroll
        for (int j = 0; j < 4; j++) O[i][j] = 0.f;
    float lsum0 = 0.f, lsum1 = 0.f;

    for (int t = 0; t < NN / TK; t++) {
        const int buf = t & 1;
        if (t + 1 < NN / TK) LOAD_TILE(buf ^ 1, (t + 1) * TK);

#pragma unroll
        for (int kg = 0; kg < 2; kg++) {          // two 16-key groups
            // ---- K B-fragments via direct LDS.32 (PTX m16n8k16 B layout:
            //      R0={B[2t][n],B[2t+1][n]}, R1=k+8; B[k][n] = K[key n][d k]) ----
            const char* kbh = smem + KS_OFF + buf * 5120;    // hi limb
            const char* kbl = kbh + 2560;                    // lo limb
            const int r0 = (kg * 16 + lq) * 80;              // keys n=lq (0-7)
            const int r8 = r0 + 640;                         // keys 8-15
            const int db = 4 * lr;
            uint32_t kh[8], kl[8];
            kh[0] = *(const uint32_t*)(kbh + r0 + db);        // e0 ks0 b0
            kh[1] = *(const uint32_t*)(kbh + r0 + db + 16);   // e0 ks0 b1
            kh[2] = *(const uint32_t*)(kbh + r0 + db + 32);   // e0 ks1 b0
            kh[3] = *(const uint32_t*)(kbh + r0 + db + 48);   // e0 ks1 b1
            kh[4] = *(const uint32_t*)(kbh + r8 + db);        // e1 ks0 b0
            kh[5] = *(const uint32_t*)(kbh + r8 + db + 16);
            kh[6] = *(const uint32_t*)(kbh + r8 + db + 32);
            kh[7] = *(const uint32_t*)(kbh + r8 + db + 48);
            kl[0] = *(const uint32_t*)(kbl + r0 + db);
            kl[1] = *(const uint32_t*)(kbl + r0 + db + 16);
            kl[2] = *(const uint32_t*)(kbl + r0 + db + 32);
            kl[3] = *(const uint32_t*)(kbl + r0 + db + 48);
            kl[4] = *(const uint32_t*)(kbl + r8 + db);
            kl[5] = *(const uint32_t*)(kbl + r8 + db + 16);
            kl[6] = *(const uint32_t*)(kbl + r8 + db + 32);
            kl[7] = *(const uint32_t*)(kbl + r8 + db + 48);

            float e0[4] = {0,0,0,0}, e1[4] = {0,0,0,0};
            // hh
            mma_bf16(e0, QH[0], kh[0], kh[1]);
            mma_bf16(e0, QH[1], kh[2], kh[3]);
            mma_bf16(e1, QH[0], kh[4], kh[5]);
            mma_bf16(e1, QH[1], kh[6], kh[7]);
            // lh (Q lo x K hi)
            mma_bf16(e0, QL[0], kh[0], kh[1]);
            mma_bf16(e0, QL[1], kh[2], kh[3]);
            mma_bf16(e1, QL[0], kh[4], kh[5]);
            mma_bf16(e1, QL[1], kh[6], kh[7]);
            // hl (Q hi x K lo)
            mma_bf16(e0, QH[0], kl[0], kl[1]);
            mma_bf16(e0, QH[1], kl[2], kl[3]);
            mma_bf16(e1, QH[0], kl[4], kl[5]);
            mma_bf16(e1, QH[1], kl[6], kl[7]);

            // ---- softmax numerators + bf16 split P fragments (R9 code) ----
            float p00 = __expf(e0[0]), p01 = __expf(e0[1]);
            float p02 = __expf(e0[2]), p03 = __expf(e0[3]);
            float p10 = __expf(e1[0]), p11 = __expf(e1[1]);
            float p12 = __expf(e1[2]), p13 = __expf(e1[3]);
            lsum0 += p00 + p01 + p10 + p11;
            lsum1 += p02 + p03 + p12 + p13;

            uint32_t PH[4], PL[4];
            {
                float h0, h1;
                h0 = bfh(p00); h1 = bfh(p01);
                PH[0] = bf2pack(h0, h1); PL[0] = bf2pack(p00 - h0, p01 - h1);
                h0 = bfh(p02); h1 = bfh(p03);
                PH[1] = bf2pack(h0, h1); PL[1] = bf2pack(p02 - h0, p03 - h1);
                h0 = bfh(p10); h1 = bfh(p11);
                PH[2] = bf2pack(h0, h1); PL[2] = bf2pack(p10 - h0, p11 - h1);
                h0 = bfh(p12); h1 = bfh(p13);
                PH[3] = bf2pack(h0, h1); PL[3] = bf2pack(p12 - h0, p13 - h1);
            }

            // ---- PV: bf16x2 over 128 channels (R9-validated, non-trans ldsm4) ----
            const int chL  = cg * 128 + ((g >> 1) << 3) + gr;   // + np*16
            const int kblk = kg * 2 + (g & 1);
#pragma unroll
            for (int np = 0; np < 8; np++) {
                int ch = chL + np * 16;
                uint32_t row_off = (uint32_t)(ch * 64 + ((kblk ^ (ch & 3)) * 16));
                uint32_t ah = sb + VS_OFF + (buf * 2 + 0) * 16384 + row_off;
                uint32_t al = sb + VS_OFF + (buf * 2 + 1) * 16384 + row_off;
                uint32_t vh[4], vl[4];
                ldsm4(vh, ah);
                ldsm4(vl, al);
#pragma unroll
                for (int u = 0; u < 2; u++) {
                    float* o = O[np * 2 + u];
                    mma_bf16(o, PH, vh[2*u], vh[2*u + 1]);
                    mma_bf16(o, PH, vl[2*u], vl[2*u + 1]);
                    mma_bf16(o, PL, vh[2*u], vh[2*u + 1]);
                }
            }
        }
        __syncthreads();
    }

    // ---- row-sum reduce over lane quads ----
    lsum0 += __shfl_xor_sync(0xffffffffu, lsum0, 1);
    lsum0 += __shfl_xor_sync(0xffffffffu, lsum0, 2);
    lsum1 += __shfl_xor_sync(0xffffffffu, lsum1, 1);
    lsum1 += __shfl_xor_sync(0xffffffffu, lsum1, 2);
    const float inv0 = 1.0f / lsum0;
    const float inv1 = 1.0f / lsum1;
    const float gm = __ldg(gamma);

    // ---- epilogue: quantize into smem staging [256 ch][68], coalesced store ----
    float* stg = (float*)smem;
    __syncthreads();
#pragma unroll
    for (int oc = 0; oc < 16; oc++) {
        int ch = cg * 128 + oc * 8 + lr * 2;
        int r0 = mg * 16 + lq, r1 = r0 + 8;
        float o0 = O[oc][0] * inv0, o1 = O[oc][1] * inv0;
        float o2 = O[oc][2] * inv1, o3 = O[oc][3] * inv1;
        stg[ ch      * 68 + r0] = floorf((gm * o0 + o0) * 256.f) * 0.00390625f;
        stg[(ch + 1) * 68 + r0] = floorf((gm * o1 + o1) * 256.f) * 0.00390625f;
        stg[ ch      * 68 + r1] = floorf((gm * o2 + o2) * 256.f) * 0.00390625f;
        stg[(ch + 1) * 68 + r1] = floorf((gm * o3 + o3) * 256.f) * 0.00390625f;
    }
    __syncthreads();
#pragma unroll
    for (int i = 0; i < 16; i++) {
        int ch = (tid >> 4) + i * 16;
        int r4 = (tid & 15) * 4;
        *(float4*)&out[((size_t)b * NC + ch) * NN + n0 + r4] = *(float4*)&stg[ch * 68 + r4];
    }
}

// ---------------- launch ----------------
extern "C" void kernel_launch(void* const* d_in, const int* in_sizes, int n_in,
                              void* d_out, int out_size)
{
    const float* x     = (const float*)d_in[0];
    const float* wq    = (const float*)d_in[1];
    const float* bq    = (const float*)d_in[2];
    const float* wk    = (const float*)d_in[3];
    const float* bk    = (const float*)d_in[4];
    const float* wv    = (const float*)d_in[5];
    const float* bv    = (const float*)d_in[6];
    const float* gamma = (const float*)d_in[7];
    float* out = (float*)d_out;

    dim3 gp(NN / 256, 10, NB);
    proj_kernel<<<gp, 256>>>(x, wq, bq, wk, bk, wv, bv);

    dim3 gt(NN / 64, 2, NB);
    tsplit_kernel<<<gt, 256>>>();

    cudaFuncSetAttribute(attn_kernel, cudaFuncAttributeMaxDynamicSharedMemorySize, SMEM_BYTES);
    dim3 ga(NN / MR, NB);
    attn_kernel<<<ga, 256, SMEM_BYTES>>>(out, gamma);
}

// round 11
// speedup vs baseline: 3.1139x; 1.1544x over previous
#include <cuda_runtime.h>
#include <cuda_bf16.h>
#include <cstdint>

#define NB  8
#define NC  256
#define NCQ 32
#define NN  4096
#define MR  128     // query rows per CTA
#define TK  32      // keys per gmem tile
#define NT  512     // threads per CTA

// ---------------- scratch (no allocs allowed) ----------------
__device__ float g_q[NB * NCQ * NN];            // [b][d][n]
__device__ float g_k[NB * NCQ * NN];            // [b][d][n]
__device__ alignas(16) __nv_bfloat16 qth[NB * NN * 32];  // [b][n][d] bf16 hi
__device__ alignas(16) __nv_bfloat16 qtl[NB * NN * 32];  // residual
__device__ alignas(16) __nv_bfloat16 kth[NB * NN * 32];
__device__ alignas(16) __nv_bfloat16 ktl[NB * NN * 32];
__device__ alignas(16) __nv_bfloat16 vv_h[NB * NC * NN]; // [b][ch][n] bf16-hi
__device__ alignas(16) __nv_bfloat16 vv_l[NB * NC * NN]; // bf16 residual

// ---------------- helpers ----------------
__device__ __forceinline__ uint32_t smem_u32(const void* p) {
    uint32_t a;
    asm("{ .reg .u64 t; cvta.to.shared.u64 t, %1; cvt.u32.u64 %0, t; }" : "=r"(a) : "l"(p));
    return a;
}
__device__ __forceinline__ uint32_t bf2pack(float lo, float hi) {
    uint32_t r;
    asm("cvt.rn.bf16x2.f32 %0, %1, %2;" : "=r"(r) : "f"(hi), "f"(lo));
    return r;
}
__device__ __forceinline__ float bfh(float x) {
    return __bfloat162float(__float2bfloat16(x));
}
__device__ __forceinline__ unsigned long long pack2(float a, float b) {
    unsigned long long r;
    asm("mov.b64 %0, {%1, %2};" : "=l"(r) : "f"(a), "f"(b));
    return r;
}
__device__ __forceinline__ void fma2(unsigned long long& d, unsigned long long a, unsigned long long b) {
    asm("fma.rn.f32x2 %0, %1, %2, %0;" : "+l"(d) : "l"(a), "l"(b));
}
__device__ __forceinline__ float2 unpack2(unsigned long long v) {
    float lo, hi;
    asm("mov.b64 {%0, %1}, %2;" : "=f"(lo), "=f"(hi) : "l"(v));
    return make_float2(lo, hi);
}
__device__ __forceinline__ void mma_bf16(float* c, const uint32_t* a,
                                         uint32_t b0, uint32_t b1) {
    asm volatile(
        "mma.sync.aligned.m16n8k16.row.col.f32.bf16.bf16.f32 "
        "{%0,%1,%2,%3},{%4,%5,%6,%7},{%8,%9},{%0,%1,%2,%3};"
        : "+f"(c[0]), "+f"(c[1]), "+f"(c[2]), "+f"(c[3])
        : "r"(a[0]), "r"(a[1]), "r"(a[2]), "r"(a[3]), "r"(b0), "r"(b1));
}
// R4/R9-validated helper: NON-trans ldmatrix.
__device__ __forceinline__ void ldsm4(uint32_t* r, uint32_t addr) {
    asm volatile("ldmatrix.sync.aligned.m8n8.x4.shared.b16 {%0,%1,%2,%3},[%4];"
                 : "=r"(r[0]), "=r"(r[1]), "=r"(r[2]), "=r"(r[3]) : "r"(addr));
}
__device__ __forceinline__ void cpa16(uint32_t dst, const void* src) {
    asm volatile("cp.async.cg.shared.global [%0], [%1], 16;" :: "r"(dst), "l"(src));
}
__device__ __forceinline__ void cpa8(uint32_t dst, const void* src) {
    asm volatile("cp.async.ca.shared.global [%0], [%1], 8;" :: "r"(dst), "l"(src));
}
#define CP_COMMIT() asm volatile("cp.async.commit_group;" ::: "memory")
#define CP_WAIT0()  asm volatile("cp.async.wait_group 0;" ::: "memory")

// ---------------- projection kernel (byte-identical to R10) -----------------
__global__ void __launch_bounds__(256) proj_kernel(
    const float* __restrict__ x,
    const float* __restrict__ wq, const float* __restrict__ bq,
    const float* __restrict__ wk, const float* __restrict__ bk,
    const float* __restrict__ wv, const float* __restrict__ bv)
{
    __shared__ float xs[32][256];
    __shared__ float ws[32][33];

    const int b  = blockIdx.z;
    const int n0 = blockIdx.x * 256;
    const int o0 = blockIdx.y * 32;
    const int tid = threadIdx.x;
    const int tx = tid & 63;
    const int ty = tid >> 6;

    unsigned long long accp[8][2];
#pragma unroll
    for (int i = 0; i < 8; i++) { accp[i][0] = 0ull; accp[i][1] = 0ull; }

    for (int cc = 0; cc < NC; cc += 32) {
        __syncthreads();
#pragma unroll
        for (int p = 0; p < 8; p++) {
            int idx = tid + p * 256;
            int c  = idx >> 6;
            int n4 = idx & 63;
            *(float4*)&xs[c][n4 * 4] =
                *(const float4*)&x[(size_t)(b * NC + cc + c) * NN + n0 + n4 * 4];
        }
#pragma unroll
        for (int p = 0; p < 4; p++) {
            int idx = tid + p * 256;
            int o  = idx >> 5;
            int c2 = idx & 31;
            int og = o0 + o;
            const float* wsrc;
            if (og < 32)        wsrc = wq + og * NC;
            else if (og < 64)   wsrc = wk + (og - 32) * NC;
            else                wsrc = wv + (og - 64) * NC;
            ws[o][c2] = wsrc[cc + c2];
        }
        __syncthreads();
#pragma unroll
        for (int c = 0; c < 32; c++) {
            ulonglong2 xp = *(const ulonglong2*)&xs[c][tx * 4];
#pragma unroll
            for (int i = 0; i < 8; i++) {
                float wv_ = ws[ty * 8 + i][c];
                unsigned long long w2 = pack2(wv_, wv_);
                fma2(accp[i][0], w2, xp.x);
                fma2(accp[i][1], w2, xp.y);
            }
        }
    }

    float acc[8][4];
#pragma unroll
    for (int i = 0; i < 8; i++) {
        float2 f0 = unpack2(accp[i][0]);
        float2 f1 = unpack2(accp[i][1]);
        acc[i][0] = f0.x; acc[i][1] = f0.y; acc[i][2] = f1.x; acc[i][3] = f1.y;
    }

#pragma unroll
    for (int i = 0; i < 8; i++) {
        int og = o0 + ty * 8 + i;
        if (og < 32) {
            float bias = bq[og];
            float4 v4 = make_float4(acc[i][0]+bias, acc[i][1]+bias, acc[i][2]+bias, acc[i][3]+bias);
            *(float4*)&g_q[((size_t)b * NCQ + og) * NN + n0 + tx * 4] = v4;
        } else if (og < 64) {
            float bias = bk[og - 32];
            float4 v4 = make_float4(acc[i][0]+bias, acc[i][1]+bias, acc[i][2]+bias, acc[i][3]+bias);
            *(float4*)&g_k[((size_t)b * NCQ + (og - 32)) * NN + n0 + tx * 4] = v4;
        } else {
            int ch = og - 64;
            float bias = bv[ch];
            float vals[4] = {acc[i][0]+bias, acc[i][1]+bias, acc[i][2]+bias, acc[i][3]+bias};
            uint32_t hp[2], lp[2];
#pragma unroll
            for (int p = 0; p < 2; p++) {
                float h0 = bfh(vals[2*p]), h1 = bfh(vals[2*p+1]);
                hp[p] = bf2pack(h0, h1);
                lp[p] = bf2pack(vals[2*p] - h0, vals[2*p+1] - h1);
            }
            size_t off = ((size_t)b * NC + ch) * NN + n0 + tx * 4;
            *(uint32_t*)&vv_h[off]     = hp[0];
            *(uint32_t*)&vv_h[off + 2] = hp[1];
            *(uint32_t*)&vv_l[off]     = lp[0];
            *(uint32_t*)&vv_l[off + 2] = lp[1];
        }
    }
}

// ---------------- transpose + bf16-limb split for Q, K (R10) ----------------
__global__ void __launch_bounds__(256) tsplit_kernel()
{
    __shared__ float ts[32][68];
    const int b = blockIdx.z;
    const int which = blockIdx.y;
    const int n0 = blockIdx.x * 64;
    const int tid = threadIdx.x;

    const float* src = which ? g_k : g_q;
    __nv_bfloat16* dh = which ? kth : qth;
    __nv_bfloat16* dl = which ? ktl : qtl;

#pragma unroll
    for (int i = 0; i < 2; i++) {
        int idx = tid + i * 256;
        int d  = idx >> 4;
        int n4 = (idx & 15) * 4;
        float4 v = *(const float4*)&src[((size_t)b * 32 + d) * NN + n0 + n4];
        ts[d][n4 + 0] = v.x; ts[d][n4 + 1] = v.y; ts[d][n4 + 2] = v.z; ts[d][n4 + 3] = v.w;
    }
    __syncthreads();
#pragma unroll
    for (int i = 0; i < 2; i++) {
        int idx = tid + i * 256;
        int n  = idx >> 3;
        int c4 = (idx & 7) * 4;
        float x0 = ts[c4+0][n], x1 = ts[c4+1][n], x2 = ts[c4+2][n], x3 = ts[c4+3][n];
        float h0 = bfh(x0), h1 = bfh(x1), h2 = bfh(x2), h3 = bfh(x3);
        uint2 hh = make_uint2(bf2pack(h0, h1), bf2pack(h2, h3));
        uint2 ll = make_uint2(bf2pack(x0 - h0, x1 - h1), bf2pack(x2 - h2, x3 - h3));
        size_t off = ((size_t)b * NN + n0 + n) * 32 + c4;
        *(uint2*)&dh[off] = hh;
        *(uint2*)&dl[off] = ll;
    }
}

// ---------------- fused attention kernel (MR=128, 512 thr, cp.async) --------
// smem bytes:
//   [0,     20480)  Q stage  bf16 [2 limb][128 rows][40] (80B row stride)
//   [20480, 30720)  K tiles  bf16 [2 buf][2 limb][32 keys][40]
//   [30720, 96256)  V tiles  bf16 [2 buf][2 limb][256 ch][32] (R10 layout)
//   epilogue staging [256][68] f32 reuses [0, 69632)
#define QS_OFF 0
#define QL_REL 10240
#define KS_OFF 20480
#define VS_OFF 30720
#define SMEM_BYTES 96256

__global__ void __launch_bounds__(NT, 1) attn_kernel(float* __restrict__ out,
                                                     const float* __restrict__ gamma)
{
    extern __shared__ char smem[];
    const uint32_t sb = smem_u32(smem);

    const int b    = blockIdx.y;
    const int n0   = blockIdx.x * MR;
    const int tid  = threadIdx.x;
    const int w    = tid >> 5;
    const int lane = tid & 31;
    const int mg   = w >> 1;          // row group 0..7 (16 rows each)
    const int cg   = w & 1;           // channel group 0..1 (128 ch each)
    const int lq   = lane >> 2;       // lane/4
    const int lr   = lane & 3;        // lane%4
    const int g    = lane >> 3;       // ldmatrix group
    const int gr   = lane & 7;

    // ---- stage Q (both limbs): 128 rows x 4 segs, one per thread ----
    {
        int row = tid >> 2, seg = tid & 3;
        size_t go = ((size_t)b * NN + n0 + row) * 32 + seg * 8;
        *(uint4*)(smem + QS_OFF +          row * 80 + seg * 16) = *(const uint4*)&qth[go];
        *(uint4*)(smem + QS_OFF + QL_REL + row * 80 + seg * 16) = *(const uint4*)&qtl[go];
    }

    // ---- async tile loads: K (1 x 8B per thread) + V (4 x 16B per thread) ----
#define LOAD_TILE(BUF, M1) do { \
    { \
        int limb = tid >> 8; \
        int rem  = tid & 255; \
        int key  = rem >> 3, dseg = rem & 7; \
        const __nv_bfloat16* ksrc = limb ? ktl : kth; \
        cpa8(sb + KS_OFF + (BUF) * 5120 + limb * 2560 + key * 80 + dseg * 8, \
             &ksrc[((size_t)b * NN + (M1) + key) * 32 + dseg * 4]); \
    } \
    _Pragma("unroll") \
    for (int i = 0; i < 4; i++) { \
        int idx = tid + i * NT; \
        int vl  = idx >> 10; \
        int r2  = idx & 1023; \
        int ch  = r2 >> 2, kq = r2 & 3; \
        int kqs = kq ^ (ch & 3); \
        const __nv_bfloat16* vsrc = vl ? vv_l : vv_h; \
        cpa16(sb + VS_OFF + ((BUF) * 2 + vl) * 16384 + ch * 64 + kqs * 16, \
              &vsrc[((size_t)b * NC + ch) * NN + (M1) + kq * 8]); \
    } \
    CP_COMMIT(); \
} while (0)

    LOAD_TILE(0, 0);
    CP_WAIT0();
    __syncthreads();

    // ---- hoist Q A-fragments via direct LDS.32 (validated R10 path) ----
    uint32_t QH[2][4], QL[2][4];
    {
        const char* q0 = smem + QS_OFF + (mg * 16 + lq) * 80;
        const char* q8 = q0 + 8 * 80;
#pragma unroll
        for (int ks = 0; ks < 2; ks++) {
            int d0 = (ks * 16 + 2 * lr) * 2;   // byte offset, 4B aligned
            QH[ks][0] = *(const uint32_t*)(q0 + d0);
            QH[ks][1] = *(const uint32_t*)(q8 + d0);
            QH[ks][2] = *(const uint32_t*)(q0 + d0 + 16);
            QH[ks][3] = *(const uint32_t*)(q8 + d0 + 16);
            QL[ks][0] = *(const uint32_t*)(q0 + QL_REL + d0);
            QL[ks][1] = *(const uint32_t*)(q8 + QL_REL + d0);
            QL[ks][2] = *(const uint32_t*)(q0 + QL_REL + d0 + 16);
            QL[ks][3] = *(const uint32_t*)(q8 + QL_REL + d0 + 16);
        }
    }

    float O[16][4];
#pragma unroll
    for (int i = 0; i < 16; i++)
#pragma unroll
        for (int j = 0; j < 4; j++) O[i][j] = 0.f;
    float lsum0 = 0.f, lsum1 = 0.f;

    for (int t = 0; t < NN / TK; t++) {
        const int buf = t & 1;
        if (t + 1 < NN / TK) LOAD_TILE(buf ^ 1, (t + 1) * TK);

#pragma unroll
        for (int kg = 0; kg < 2; kg++) {          // two 16-key groups
            // ---- K B-fragments via direct LDS.32 (validated R10 path) ----
            const char* kbh = smem + KS_OFF + buf * 5120;    // hi limb
            const char* kbl = kbh + 2560;                    // lo limb
            const int r0 = (kg * 16 + lq) * 80;              // keys n=lq (0-7)
            const int r8 = r0 + 640;                         // keys 8-15
            const int db = 4 * lr;
            uint32_t kh[8], kl[8];
            kh[0] = *(const uint32_t*)(kbh + r0 + db);
            kh[1] = *(const uint32_t*)(kbh + r0 + db + 16);
            kh[2] = *(const uint32_t*)(kbh + r0 + db + 32);
            kh[3] = *(const uint32_t*)(kbh + r0 + db + 48);
            kh[4] = *(const uint32_t*)(kbh + r8 + db);
            kh[5] = *(const uint32_t*)(kbh + r8 + db + 16);
            kh[6] = *(const uint32_t*)(kbh + r8 + db + 32);
            kh[7] = *(const uint32_t*)(kbh + r8 + db + 48);
            kl[0] = *(const uint32_t*)(kbl + r0 + db);
            kl[1] = *(const uint32_t*)(kbl + r0 + db + 16);
            kl[2] = *(const uint32_t*)(kbl + r0 + db + 32);
            kl[3] = *(const uint32_t*)(kbl + r0 + db + 48);
            kl[4] = *(const uint32_t*)(kbl + r8 + db);
            kl[5] = *(const uint32_t*)(kbl + r8 + db + 16);
            kl[6] = *(const uint32_t*)(kbl + r8 + db + 32);
            kl[7] = *(const uint32_t*)(kbl + r8 + db + 48);

            float e0[4] = {0,0,0,0}, e1[4] = {0,0,0,0};
            // hh
            mma_bf16(e0, QH[0], kh[0], kh[1]);
            mma_bf16(e0, QH[1], kh[2], kh[3]);
            mma_bf16(e1, QH[0], kh[4], kh[5]);
            mma_bf16(e1, QH[1], kh[6], kh[7]);
            // lh (Q lo x K hi)
            mma_bf16(e0, QL[0], kh[0], kh[1]);
            mma_bf16(e0, QL[1], kh[2], kh[3]);
            mma_bf16(e1, QL[0], kh[4], kh[5]);
            mma_bf16(e1, QL[1], kh[6], kh[7]);
            // hl (Q hi x K lo)
            mma_bf16(e0, QH[0], kl[0], kl[1]);
            mma_bf16(e0, QH[1], kl[2], kl[3]);
            mma_bf16(e1, QH[0], kl[4], kl[5]);
            mma_bf16(e1, QH[1], kl[6], kl[7]);

            // ---- softmax numerators + bf16 split P fragments ----
            float p00 = __expf(e0[0]), p01 = __expf(e0[1]);
            float p02 = __expf(e0[2]), p03 = __expf(e0[3]);
            float p10 = __expf(e1[0]), p11 = __expf(e1[1]);
            float p12 = __expf(e1[2]), p13 = __expf(e1[3]);
            lsum0 += p00 + p01 + p10 + p11;
            lsum1 += p02 + p03 + p12 + p13;

            uint32_t PH[4], PL[4];
            {
                float h0, h1;
                h0 = bfh(p00); h1 = bfh(p01);
                PH[0] = bf2pack(h0, h1); PL[0] = bf2pack(p00 - h0, p01 - h1);
                h0 = bfh(p02); h1 = bfh(p03);
                PH[1] = bf2pack(h0, h1); PL[1] = bf2pack(p02 - h0, p03 - h1);
                h0 = bfh(p10); h1 = bfh(p11);
                PH[2] = bf2pack(h0, h1); PL[2] = bf2pack(p10 - h0, p11 - h1);
                h0 = bfh(p12); h1 = bfh(p13);
                PH[3] = bf2pack(h0, h1); PL[3] = bf2pack(p12 - h0, p13 - h1);
            }

            // ---- PV: bf16x2 over 128 channels (validated non-trans ldsm4) ----
            const int chL  = cg * 128 + ((g >> 1) << 3) + gr;   // + np*16
            const int kblk = kg * 2 + (g & 1);
#pragma unroll
            for (int np = 0; np < 8; np++) {
                int ch = chL + np * 16;
                uint32_t row_off = (uint32_t)(ch * 64 + ((kblk ^ (ch & 3)) * 16));
                uint32_t ah = sb + VS_OFF + (buf * 2 + 0) * 16384 + row_off;
                uint32_t al = sb + VS_OFF + (buf * 2 + 1) * 16384 + row_off;
                uint32_t vh[4], vl[4];
                ldsm4(vh, ah);
                ldsm4(vl, al);
#pragma unroll
                for (int u = 0; u < 2; u++) {
                    float* o = O[np * 2 + u];
                    mma_bf16(o, PH, vh[2*u], vh[2*u + 1]);
                    mma_bf16(o, PH, vl[2*u], vl[2*u + 1]);
                    mma_bf16(o, PL, vh[2*u], vh[2*u + 1]);
                }
            }
        }
        CP_WAIT0();
        __syncthreads();
    }

    // ---- row-sum reduce over lane quads ----
    lsum0 += __shfl_xor_sync(0xffffffffu, lsum0, 1);
    lsum0 += __shfl_xor_sync(0xffffffffu, lsum0, 2);
    lsum1 += __shfl_xor_sync(0xffffffffu, lsum1, 1);
    lsum1 += __shfl_xor_sync(0xffffffffu, lsum1, 2);
    const float inv0 = 1.0f / lsum0;
    const float inv1 = 1.0f / lsum1;
    const float gm = __ldg(gamma);

    // ---- epilogue: two 64-row passes through [256][68] f32 staging ----
    float* stg = (float*)smem;
#pragma unroll
    for (int half = 0; half < 2; half++) {
        __syncthreads();
        if ((mg >> 2) == half) {
#pragma unroll
            for (int oc = 0; oc < 16; oc++) {
                int ch = cg * 128 + oc * 8 + lr * 2;
                int r0 = mg * 16 + lq - half * 64, r1 = r0 + 8;
                float o0 = O[oc][0] * inv0, o1 = O[oc][1] * inv0;
                float o2 = O[oc][2] * inv1, o3 = O[oc][3] * inv1;
                stg[ ch      * 68 + r0] = floorf((gm * o0 + o0) * 256.f) * 0.00390625f;
                stg[(ch + 1) * 68 + r0] = floorf((gm * o1 + o1) * 256.f) * 0.00390625f;
                stg[ ch      * 68 + r1] = floorf((gm * o2 + o2) * 256.f) * 0.00390625f;
                stg[(ch + 1) * 68 + r1] = floorf((gm * o3 + o3) * 256.f) * 0.00390625f;
            }
        }
        __syncthreads();
#pragma unroll
        for (int i = 0; i < 8; i++) {
            int ch = (tid >> 4) + i * 32;
            int r4 = (tid & 15) * 4;
            *(float4*)&out[((size_t)b * NC + ch) * NN + n0 + half * 64 + r4] =
                *(float4*)&stg[ch * 68 + r4];
        }
    }
}

// ---------------- launch ----------------
extern "C" void kernel_launch(void* const* d_in, const int* in_sizes, int n_in,
                              void* d_out, int out_size)
{
    const float* x     = (const float*)d_in[0];
    const float* wq    = (const float*)d_in[1];
    const float* bq    = (const float*)d_in[2];
    const float* wk    = (const float*)d_in[3];
    const float* bk    = (const float*)d_in[4];
    const float* wv    = (const float*)d_in[5];
    const float* bv    = (const float*)d_in[6];
    const float* gamma = (const float*)d_in[7];
    float* out = (float*)d_out;

    dim3 gp(NN / 256, 10, NB);
    proj_kernel<<<gp, 256>>>(x, wq, bq, wk, bk, wv, bv);

    dim3 gt(NN / 64, 2, NB);
    tsplit_kernel<<<gt, 256>>>();

    cudaFuncSetAttribute(attn_kernel, cudaFuncAttributeMaxDynamicSharedMemorySize, SMEM_BYTES);
    dim3 ga(NN / MR, NB);
    attn_kernel<<<ga, NT, SMEM_BYTES>>>(out, gamma);
}